// round 13
// baseline (speedup 1.0000x reference)
#include <cuda_runtime.h>
#include <cuda_bf16.h>
#include <math.h>

#define SQ   2048
#define CCH  2048
#define NH   16
#define HD   128
#define BLKS 64
#define NB   32
#define THRP 0.8f
#define EPSV 1e-6f

// ---------------- scratch (device globals; no allocation allowed) -------------
__device__ float g_q[SQ * CCH];
__device__ float g_k[SQ * CCH];
__device__ float g_qb[NH * NB * HD];
__device__ float g_kb[NH * NB * HD];
__device__ unsigned char g_mask[NH * NB * NB];

__device__ unsigned short g_xh[SQ * CCH];
__device__ unsigned short g_xl[SQ * CCH];
__device__ unsigned short g_ah[SQ * CCH];
__device__ unsigned short g_al[SQ * CCH];
__device__ unsigned short g_qsh[SQ * CCH];
__device__ unsigned short g_qsl[SQ * CCH];
__device__ unsigned short g_ksh[SQ * CCH];
__device__ unsigned short g_ksl[SQ * CCH];
__device__ unsigned short g_vsh[SQ * CCH];
__device__ unsigned short g_vsl[SQ * CCH];
__device__ unsigned short g_wqh[CCH * CCH];
__device__ unsigned short g_wql[CCH * CCH];
__device__ unsigned short g_wkh[CCH * CCH];
__device__ unsigned short g_wkl[CCH * CCH];
__device__ unsigned short g_wvh[CCH * CCH];
__device__ unsigned short g_wvl[CCH * CCH];
__device__ unsigned short g_woh[CCH * CCH];
__device__ unsigned short g_wol[CCH * CCH];

// ================= helpers ======================================================
__device__ __forceinline__ unsigned pack_bf16x2(float lo, float hi) {
    unsigned r;
    asm("cvt.rn.bf16x2.f32 %0, %1, %2;" : "=r"(r) : "f"(hi), "f"(lo));
    return r;
}
__device__ __forceinline__ unsigned smem_u32(const void* p) {
    unsigned a;
    asm("{ .reg .u64 t; cvta.to.shared.u64 t, %1; cvt.u32.u64 %0, t; }" : "=r"(a) : "l"(p));
    return a;
}
__device__ __forceinline__ void mma_bf16(float* c, const unsigned* a, const unsigned* b)
{
    asm volatile(
        "mma.sync.aligned.m16n8k16.row.col.f32.bf16.bf16.f32 "
        "{%0,%1,%2,%3}, {%4,%5,%6,%7}, {%8,%9}, {%0,%1,%2,%3};"
        : "+f"(c[0]), "+f"(c[1]), "+f"(c[2]), "+f"(c[3])
        : "r"(a[0]), "r"(a[1]), "r"(a[2]), "r"(a[3]), "r"(b[0]), "r"(b[1]));
}
__device__ __forceinline__ void ldsm_x4(unsigned& r0, unsigned& r1, unsigned& r2, unsigned& r3,
                                        unsigned addr)
{
    asm volatile("ldmatrix.sync.aligned.m8n8.x4.shared.b16 {%0,%1,%2,%3}, [%4];"
                 : "=r"(r0), "=r"(r1), "=r"(r2), "=r"(r3) : "r"(addr));
}
__device__ __forceinline__ void ldsm_x4_t(unsigned& r0, unsigned& r1, unsigned& r2, unsigned& r3,
                                          unsigned addr)
{
    asm volatile("ldmatrix.sync.aligned.m8n8.x4.trans.shared.b16 {%0,%1,%2,%3}, [%4];"
                 : "=r"(r0), "=r"(r1), "=r"(r2), "=r"(r3) : "r"(addr));
}
__device__ __forceinline__ void cp16(unsigned sm, const void* g) {
    asm volatile("cp.async.cg.shared.global [%0], [%1], 16;" :: "r"(sm), "l"(g));
}
#define CP_COMMIT() asm volatile("cp.async.commit_group;" ::: "memory")
#define CP_WAIT0()  asm volatile("cp.async.wait_group 0;" ::: "memory")
#define CP_WAIT1()  asm volatile("cp.async.wait_group 1;" ::: "memory")

// ================= fp32 -> bf16 hi/lo split ====================================
__global__ void split_bf16(const float* __restrict__ a, unsigned short* __restrict__ h,
                           unsigned short* __restrict__ l, int n)
{
    int i = blockIdx.x * 256 + threadIdx.x;
    if (i < n) {
        float v = a[i];
        __nv_bfloat16 hi = __float2bfloat16(v);
        __nv_bfloat16 lo = __float2bfloat16(v - __bfloat162float(hi));
        h[i] = __bfloat16_as_ushort(hi);
        l[i] = __bfloat16_as_ushort(lo);
    }
}

// ================= transpose + split (4 weights in one launch) ==================
struct TransPtrs {
    const float* w[4];
    unsigned short* th[4];
    unsigned short* tl[4];
};

__global__ void transpose_split4(TransPtrs P)
{
    __shared__ float t[32][33];
    int z = blockIdx.z;
    const float* W = P.w[z];
    unsigned short* Th = P.th[z];
    unsigned short* Tl = P.tl[z];
    int bx = blockIdx.x * 32, by = blockIdx.y * 32;
    int tx = threadIdx.x, ty = threadIdx.y;
    t[ty][tx] = W[(size_t)(by + ty) * CCH + bx + tx];
    __syncthreads();
    float v = t[tx][ty];
    __nv_bfloat16 hi = __float2bfloat16(v);
    __nv_bfloat16 lo = __float2bfloat16(v - __bfloat162float(hi));
    size_t o = (size_t)(bx + ty) * CCH + by + tx;
    Th[o] = __bfloat16_as_ushort(hi);
    Tl[o] = __bfloat16_as_ushort(lo);
}

// ================= HMMA bf16x3 GEMM, 128x128 tile, cp.async 2-stage =============
// ldmatrix frag loads; MMA passes issued pass-major (16 independent per pass).
#define BM 128
#define BN 128
#define BK 32
#define ASTR 40
#define TILE_U16 (128 * ASTR)
#define STAGE_U16 (4 * TILE_U16)
#define G2SMEM (2 * STAGE_U16 * 2)

__global__ __launch_bounds__(256, 2) void gemm_tc(
    const unsigned short* __restrict__ Ah, const unsigned short* __restrict__ Al,
    const unsigned short* __restrict__ Bh, const unsigned short* __restrict__ Bl,
    const float* __restrict__ bias, float* __restrict__ Co,
    unsigned short* __restrict__ OH, unsigned short* __restrict__ OL)
{
    extern __shared__ __align__(16) unsigned short smg[];
    unsigned sbase = smem_u32(smg);

    int tid = threadIdx.x, w = tid >> 5, lane = tid & 31;
    int g = lane >> 2, tc2 = (lane & 3) * 2;
    int m0 = blockIdx.y * BM, n0 = blockIdx.x * BN;
    int wm = (w >> 2) * 64, wn = (w & 3) * 32;

    float acc[4][4][4];
#pragma unroll
    for (int i = 0; i < 4; i++)
#pragma unroll
        for (int j = 0; j < 4; j++)
#pragma unroll
            for (int l = 0; l < 4; l++) acc[i][j][l] = 0.f;

    int r0l = tid >> 2, c0l = (tid & 3) * 8;
    int r1l = (tid + 256) >> 2, c1l = ((tid + 256) & 3) * 8;

    unsigned aoffb = (unsigned)(((wm + (lane & 15)) * ASTR + ((lane >> 1) & 8)) * 2);
    unsigned boffb = (unsigned)(((wn + (lane & 7) + ((lane >> 1) & 8)) * ASTR + (lane & 8)) * 2);

    const int NCK = CCH / BK;

#define LOAD_STAGE(CK, SOFF)                                                        \
    {                                                                               \
        int kb = (CK) * BK;                                                         \
        unsigned s0 = sbase + (SOFF) + (unsigned)(r0l * ASTR + c0l) * 2u;           \
        unsigned s1 = sbase + (SOFF) + (unsigned)(r1l * ASTR + c1l) * 2u;           \
        size_t ga0 = (size_t)(m0 + r0l) * CCH + kb + c0l;                           \
        size_t ga1 = (size_t)(m0 + r1l) * CCH + kb + c1l;                           \
        size_t gb0 = (size_t)(n0 + r0l) * CCH + kb + c0l;                           \
        size_t gb1 = (size_t)(n0 + r1l) * CCH + kb + c1l;                           \
        cp16(s0, Ah + ga0);                                                         \
        cp16(s1, Ah + ga1);                                                         \
        cp16(s0 + TILE_U16 * 2u, Al + ga0);                                         \
        cp16(s1 + TILE_U16 * 2u, Al + ga1);                                         \
        cp16(s0 + 2u * TILE_U16 * 2u, Bh + gb0);                                    \
        cp16(s1 + 2u * TILE_U16 * 2u, Bh + gb1);                                    \
        cp16(s0 + 3u * TILE_U16 * 2u, Bl + gb0);                                    \
        cp16(s1 + 3u * TILE_U16 * 2u, Bl + gb1);                                    \
    }

    LOAD_STAGE(0, 0u);
    CP_COMMIT();

    for (int ck = 0; ck < NCK; ck++) {
        if (ck + 1 < NCK) {
            LOAD_STAGE(ck + 1, (unsigned)(((ck + 1) & 1) * STAGE_U16 * 2));
            CP_COMMIT();
            CP_WAIT1();
        } else {
            CP_WAIT0();
        }
        __syncthreads();

        unsigned stage = sbase + (unsigned)((ck & 1) * STAGE_U16 * 2);
        unsigned aH = stage + aoffb;
        unsigned bH = stage + 2u * TILE_U16 * 2u + boffb;

#pragma unroll
        for (int ks = 0; ks < BK; ks += 16) {
            unsigned ksb = (unsigned)(ks * 2);
            unsigned ah[4][4], al[4][4], bh[4][2], bl[4][2];
#pragma unroll
            for (int mf = 0; mf < 4; mf++) {
                unsigned ra = aH + (unsigned)(mf * 16 * ASTR * 2) + ksb;
                ldsm_x4(ah[mf][0], ah[mf][1], ah[mf][2], ah[mf][3], ra);
                ldsm_x4(al[mf][0], al[mf][1], al[mf][2], al[mf][3], ra + TILE_U16 * 2u);
            }
#pragma unroll
            for (int np = 0; np < 2; np++) {
                unsigned rb = bH + (unsigned)(np * 16 * ASTR * 2) + ksb;
                ldsm_x4(bh[2 * np][0], bh[2 * np][1], bh[2 * np + 1][0], bh[2 * np + 1][1], rb);
                ldsm_x4(bl[2 * np][0], bl[2 * np][1], bl[2 * np + 1][0], bl[2 * np + 1][1],
                        rb + TILE_U16 * 2u);
            }
            // pass-major: 16 independent MMAs per pass (no back-to-back acc chains)
#pragma unroll
            for (int mf = 0; mf < 4; mf++)
#pragma unroll
                for (int nf = 0; nf < 4; nf++)
                    mma_bf16(acc[mf][nf], ah[mf], bh[nf]);
#pragma unroll
            for (int mf = 0; mf < 4; mf++)
#pragma unroll
                for (int nf = 0; nf < 4; nf++)
                    mma_bf16(acc[mf][nf], ah[mf], bl[nf]);
#pragma unroll
            for (int mf = 0; mf < 4; mf++)
#pragma unroll
                for (int nf = 0; nf < 4; nf++)
                    mma_bf16(acc[mf][nf], al[mf], bh[nf]);
        }
        __syncthreads();
    }

    if (OH == nullptr) {
#pragma unroll
        for (int mf = 0; mf < 4; mf++) {
            int r0 = m0 + wm + mf * 16 + g;
#pragma unroll
            for (int nf = 0; nf < 4; nf++) {
                int col = n0 + wn + nf * 8 + tc2;
                float bx = bias[col], by = bias[col + 1];
                float2 lo = make_float2(acc[mf][nf][0] + bx, acc[mf][nf][1] + by);
                float2 hi = make_float2(acc[mf][nf][2] + bx, acc[mf][nf][3] + by);
                *(float2*)(Co + (size_t)r0 * CCH + col) = lo;
                *(float2*)(Co + (size_t)(r0 + 8) * CCH + col) = hi;
            }
        }
    } else {
#pragma unroll
        for (int mf = 0; mf < 4; mf++) {
            int r0 = m0 + wm + mf * 16 + g;
#pragma unroll
            for (int nf = 0; nf < 4; nf++) {
                int col = n0 + wn + nf * 8 + tc2;
                float bx = bias[col], by = bias[col + 1];
                float v0 = acc[mf][nf][0] + bx, v1 = acc[mf][nf][1] + by;
                float v2 = acc[mf][nf][2] + bx, v3 = acc[mf][nf][3] + by;
                __nv_bfloat16 b0 = __float2bfloat16(v0), b1 = __float2bfloat16(v1);
                __nv_bfloat16 b2 = __float2bfloat16(v2), b3 = __float2bfloat16(v3);
                float q0 = v0 - __bfloat162float(b0), q1 = v1 - __bfloat162float(b1);
                float q2 = v2 - __bfloat162float(b2), q3 = v3 - __bfloat162float(b3);
                size_t olo = (size_t)r0 * CCH + col;
                size_t ohi = (size_t)(r0 + 8) * CCH + col;
                *(unsigned*)&OH[olo] =
                    ((unsigned)__bfloat16_as_ushort(b1) << 16) | __bfloat16_as_ushort(b0);
                *(unsigned*)&OH[ohi] =
                    ((unsigned)__bfloat16_as_ushort(b3) << 16) | __bfloat16_as_ushort(b2);
                *(unsigned*)&OL[olo] = pack_bf16x2(q0, q1);
                *(unsigned*)&OL[ohi] = pack_bf16x2(q2, q3);
            }
        }
    }
}

// ---------------- fused RMSNorm + RoPE + bf16 split, in-place ------------------
__global__ __launch_bounds__(256) void rmsnorm_rope_split(
    float* __restrict__ buf, const float* __restrict__ w,
    const float* __restrict__ cs, const float* __restrict__ sn,
    unsigned short* __restrict__ oh, unsigned short* __restrict__ ol)
{
    int warp = (blockIdx.x * blockDim.x + threadIdx.x) >> 5;
    int lane = threadIdx.x & 31;
    if (warp >= SQ * NH) return;
    int s = warp / NH, h = warp % NH;
    size_t base = (size_t)s * CCH + h * HD;
    float* row = buf + base;

    float x0 = row[lane], x1 = row[lane + 32], x2 = row[lane + 64], x3 = row[lane + 96];
    float ss = x0 * x0 + x1 * x1 + x2 * x2 + x3 * x3;
#pragma unroll
    for (int o = 16; o; o >>= 1) ss += __shfl_xor_sync(0xffffffffu, ss, o);
    float r = rsqrtf(ss * (1.0f / HD) + EPSV);

    float y0 = x0 * r * w[lane];
    float y1 = x1 * r * w[lane + 32];
    float y2 = x2 * r * w[lane + 64];
    float y3 = x3 * r * w[lane + 96];

    const float* cr = cs + (size_t)s * HD;
    const float* sr = sn + (size_t)s * HD;
    float z0 = y0 * cr[lane]      - y2 * sr[lane];
    float z1 = y1 * cr[lane + 32] - y3 * sr[lane + 32];
    float z2 = y2 * cr[lane + 64] + y0 * sr[lane + 64];
    float z3 = y3 * cr[lane + 96] + y1 * sr[lane + 96];

    row[lane] = z0; row[lane + 32] = z1; row[lane + 64] = z2; row[lane + 96] = z3;

    float zz[4] = {z0, z1, z2, z3};
#pragma unroll
    for (int i = 0; i < 4; i++) {
        __nv_bfloat16 hi = __float2bfloat16(zz[i]);
        __nv_bfloat16 lo = __float2bfloat16(zz[i] - __bfloat162float(hi));
        oh[base + lane + 32 * i] = __bfloat16_as_ushort(hi);
        ol[base + lane + 32 * i] = __bfloat16_as_ushort(lo);
    }
}

// ---------------- block pooling ------------------------------------------------
__global__ void pool_blocks(const float* __restrict__ buf, float* __restrict__ out)
{
    int h = blockIdx.x, b = blockIdx.y, d = threadIdx.x;
    float sum = 0.f;
#pragma unroll 8
    for (int i = 0; i < BLKS; i++)
        sum += buf[(size_t)(b * BLKS + i) * CCH + h * HD + d];
    out[((h * NB) + b) * HD + d] = sum * (1.0f / BLKS);
}

// ---------------- NABLA block mask ----------------------------------------------
__device__ __forceinline__ int sniff_sta_dtype(const unsigned int* w)
{
    bool all01 = true, allf = true;
    for (int i = 0; i < 256; i++) {
        unsigned int v = w[i];
        if (v > 1u) all01 = false;
        if (v != 0u && v != 0x3F800000u) allf = false;
    }
    if (all01) return 0;
    if (allf) return 1;
    return 2;
}

__global__ void nabla_mask(const float* __restrict__ qb, const float* __restrict__ kb,
                           const void* __restrict__ sta, unsigned char* __restrict__ mask)
{
    int h = blockIdx.x, q = blockIdx.y, k = threadIdx.x;
    __shared__ float p[NB];
    __shared__ float cutoff;
    __shared__ int sdt;
    if (k == 0) sdt = sniff_sta_dtype((const unsigned int*)sta);

    const float* qr = qb + (h * NB + q) * HD;
    const float* kr = kb + (h * NB + k) * HD;
    float dot = 0.f;
#pragma unroll 16
    for (int d = 0; d < HD; d++) dot += qr[d] * kr[d];
    p[k] = dot * 0.08838834764831845f;
    __syncthreads();
    if (k == 0) {
        float mx = -1e30f;
        for (int i = 0; i < NB; i++) mx = fmaxf(mx, p[i]);
        float sum = 0.f;
        for (int i = 0; i < NB; i++) { p[i] = expf(p[i] - mx); sum += p[i]; }
        float inv = 1.0f / sum;
        float srt[NB];
        for (int i = 0; i < NB; i++) { p[i] *= inv; srt[i] = p[i]; }
        for (int i = 1; i < NB; i++) {
            float v = srt[i];
            int j = i - 1;
            while (j >= 0 && srt[j] < v) { srt[j + 1] = srt[j]; j--; }
            srt[j + 1] = v;
        }
        float run = 0.f, co = 1e30f;
        for (int i = 0; i < NB; i++) {
            if (run < THRP) { co = srt[i]; run += srt[i]; }
        }
        cutoff = co;
    }
    __syncthreads();

    bool sta_on;
    int sidx = q * NB + k;
    if (sdt == 0)      sta_on = ((const int*)sta)[sidx] != 0;
    else if (sdt == 1) sta_on = ((const float*)sta)[sidx] != 0.0f;
    else               sta_on = ((const unsigned char*)sta)[sidx] != 0;

    unsigned char keep = (p[k] >= cutoff) || sta_on;
    mask[(h * NB + q) * NB + k] = keep;
}

// ---------------- HMMA block-sparse flash attention (cp.async pipelined) ---------
#define KSTR 136
#define FT_SMEM (4 * 64 * KSTR * 2)

__global__ __launch_bounds__(128) void flash_attn_tc(
    const unsigned short* __restrict__ qh, const unsigned short* __restrict__ ql,
    const unsigned short* __restrict__ kh, const unsigned short* __restrict__ kl,
    const unsigned short* __restrict__ vh, const unsigned short* __restrict__ vl,
    const unsigned char* __restrict__ mask,
    unsigned short* __restrict__ oh, unsigned short* __restrict__ ol)
{
    extern __shared__ __align__(16) unsigned short smu[];
    unsigned short* Kh = smu;
    unsigned short* Kl = Kh + 64 * KSTR;
    unsigned short* Vh = Kl + 64 * KSTR;
    unsigned short* Vl = Vh + 64 * KSTR;

    int qi = blockIdx.x, h = blockIdx.y;
    int tid = threadIdx.x, w = tid >> 5, lane = tid & 31;
    int g = lane >> 2, tc2 = (lane & 3) * 2;
    int wr = w * 16;

    // Q staging (uses K buffers), then extract register fragments.
    for (int idx = tid; idx < 64 * 16; idx += 128) {
        int r = idx >> 4, c = (idx & 15) * 8;
        size_t off = (size_t)(qi * 64 + r) * CCH + h * HD + c;
        *(uint4*)&Kh[r * KSTR + c] = *(const uint4*)(qh + off);
        *(uint4*)&Kl[r * KSTR + c] = *(const uint4*)(ql + off);
    }
    __syncthreads();

    unsigned qfh[8][4], qfl[8][4];
#pragma unroll
    for (int t = 0; t < 8; t++) {
        int r0 = (wr + g) * KSTR + 16 * t + tc2;
        int r8 = (wr + 8 + g) * KSTR + 16 * t + tc2;
        qfh[t][0] = *(const unsigned*)&Kh[r0];
        qfh[t][1] = *(const unsigned*)&Kh[r8];
        qfh[t][2] = *(const unsigned*)&Kh[r0 + 8];
        qfh[t][3] = *(const unsigned*)&Kh[r8 + 8];
        qfl[t][0] = *(const unsigned*)&Kl[r0];
        qfl[t][1] = *(const unsigned*)&Kl[r8];
        qfl[t][2] = *(const unsigned*)&Kl[r0 + 8];
        qfl[t][3] = *(const unsigned*)&Kl[r8 + 8];
    }
    __syncthreads();  // staging fully read before cp.async overwrites K buffers

    float acc[16][4];
#pragma unroll
    for (int nf = 0; nf < 16; nf++)
#pragma unroll
        for (int i = 0; i < 4; i++) acc[nf][i] = 0.f;
    float m0 = -1e30f, m1 = -1e30f, l0 = 0.f, l1 = 0.f;

    const unsigned char* mrowp = mask + (h * NB + qi) * NB;
    const float scl = 0.08838834764831845f;
    unsigned kh_s = smem_u32(Kh), kl_s = smem_u32(Kl);
    unsigned vh_s = smem_u32(Vh), vl_s = smem_u32(Vl);
    int lj = lane >> 3, li = lane & 7;
    unsigned ldsm_off = (unsigned)(((lj & 1) * 8 + li) * KSTR + (lj >> 1) * 8) * 2u;

#define FA_LOAD_K(B)                                                                 \
    {                                                                                \
        _Pragma("unroll")                                                            \
        for (int it = 0; it < 8; it++) {                                             \
            int idx = tid + it * 128;                                                \
            int r = idx >> 4, c = (idx & 15) * 8;                                    \
            size_t off = (size_t)((B) * 64 + r) * CCH + h * HD + c;                  \
            unsigned so = (unsigned)((r * KSTR + c) * 2);                            \
            cp16(kh_s + so, kh + off);                                               \
            cp16(kl_s + so, kl + off);                                               \
        }                                                                            \
        CP_COMMIT();                                                                 \
    }
#define FA_LOAD_V(B)                                                                 \
    {                                                                                \
        _Pragma("unroll")                                                            \
        for (int it = 0; it < 8; it++) {                                             \
            int idx = tid + it * 128;                                                \
            int r = idx >> 4, c = (idx & 15) * 8;                                    \
            size_t off = (size_t)((B) * 64 + r) * CCH + h * HD + c;                  \
            unsigned so = (unsigned)((r * KSTR + c) * 2);                            \
            cp16(vh_s + so, vh + off);                                               \
            cp16(vl_s + so, vl + off);                                               \
        }                                                                            \
        CP_COMMIT();                                                                 \
    }

    int cur = 0;
    while (cur < NB && !mrowp[cur]) cur++;
    if (cur < NB) {
        FA_LOAD_K(cur);
        FA_LOAD_V(cur);
        CP_WAIT1();        // K[cur] ready; V[cur] in flight
        __syncthreads();
    }

    while (cur < NB) {
        int nxt = cur + 1;
        while (nxt < NB && !mrowp[nxt]) nxt++;

        // ---- S = Q K^T (bf16x3); t outer so consecutive MMAs hit different sc[j] --
        float sc[8][4];
#pragma unroll
        for (int j = 0; j < 8; j++)
#pragma unroll
            for (int i = 0; i < 4; i++) sc[j][i] = 0.f;

#pragma unroll
        for (int t = 0; t < 8; t++) {
#pragma unroll
            for (int j = 0; j < 8; j++) {
                int rbase = (8 * j + g) * KSTR + 16 * t;
                unsigned bh[2], bl[2];
                bh[0] = *(const unsigned*)&Kh[rbase + tc2];
                bh[1] = *(const unsigned*)&Kh[rbase + 8 + tc2];
                bl[0] = *(const unsigned*)&Kl[rbase + tc2];
                bl[1] = *(const unsigned*)&Kl[rbase + 8 + tc2];
                mma_bf16(sc[j], qfh[t], bh);
                mma_bf16(sc[j], qfh[t], bl);
                mma_bf16(sc[j], qfl[t], bh);
            }
        }
        __syncthreads();            // all warps done reading K[cur]
        if (nxt < NB) FA_LOAD_K(nxt);   // prefetch K[nxt]

        // ---- online softmax (registers only) -------------------------------------
        float rm0 = -1e30f, rm1 = -1e30f;
#pragma unroll
        for (int j = 0; j < 8; j++) {
#pragma unroll
            for (int i = 0; i < 4; i++) sc[j][i] *= scl;
            rm0 = fmaxf(rm0, fmaxf(sc[j][0], sc[j][1]));
            rm1 = fmaxf(rm1, fmaxf(sc[j][2], sc[j][3]));
        }
        rm0 = fmaxf(rm0, __shfl_xor_sync(0xffffffffu, rm0, 1));
        rm0 = fmaxf(rm0, __shfl_xor_sync(0xffffffffu, rm0, 2));
        rm1 = fmaxf(rm1, __shfl_xor_sync(0xffffffffu, rm1, 1));
        rm1 = fmaxf(rm1, __shfl_xor_sync(0xffffffffu, rm1, 2));
        float mn0 = fmaxf(m0, rm0), mn1 = fmaxf(m1, rm1);
        float es0 = __expf(m0 - mn0), es1 = __expf(m1 - mn1);

        float rs0 = 0.f, rs1 = 0.f;
#pragma unroll
        for (int j = 0; j < 8; j++) {
            sc[j][0] = __expf(sc[j][0] - mn0);
            sc[j][1] = __expf(sc[j][1] - mn0);
            sc[j][2] = __expf(sc[j][2] - mn1);
            sc[j][3] = __expf(sc[j][3] - mn1);
            rs0 += sc[j][0] + sc[j][1];
            rs1 += sc[j][2] + sc[j][3];
        }
        rs0 += __shfl_xor_sync(0xffffffffu, rs0, 1);
        rs0 += __shfl_xor_sync(0xffffffffu, rs0, 2);
        rs1 += __shfl_xor_sync(0xffffffffu, rs1, 1);
        rs1 += __shfl_xor_sync(0xffffffffu, rs1, 2);
        l0 = l0 * es0 + rs0;
        l1 = l1 * es1 + rs1;
        m0 = mn0; m1 = mn1;
#pragma unroll
        for (int nf = 0; nf < 16; nf++) {
            acc[nf][0] *= es0; acc[nf][1] *= es0;
            acc[nf][2] *= es1; acc[nf][3] *= es1;
        }

        if (nxt < NB) { CP_WAIT1(); } else { CP_WAIT0(); }   // V[cur] ready
        __syncthreads();

        // ---- O += P V (bf16x3) ----------------------------------------------------
#pragma unroll
        for (int t = 0; t < 4; t++) {
            unsigned ph[4], pl[4];
            {
                float c00 = sc[2 * t][0], c01 = sc[2 * t][1];
                float c02 = sc[2 * t][2], c03 = sc[2 * t][3];
                float c10 = sc[2 * t + 1][0], c11 = sc[2 * t + 1][1];
                float c12 = sc[2 * t + 1][2], c13 = sc[2 * t + 1][3];
                ph[0] = pack_bf16x2(c00, c01);
                ph[1] = pack_bf16x2(c02, c03);
                ph[2] = pack_bf16x2(c10, c11);
                ph[3] = pack_bf16x2(c12, c13);
                float r00 = c00 - __bfloat162float(__float2bfloat16(c00));
                float r01 = c01 - __bfloat162float(__float2bfloat16(c01));
                float r02 = c02 - __bfloat162float(__float2bfloat16(c02));
                float r03 = c03 - __bfloat162float(__float2bfloat16(c03));
                float r10 = c10 - __bfloat162float(__float2bfloat16(c10));
                float r11 = c11 - __bfloat162float(__float2bfloat16(c11));
                float r12 = c12 - __bfloat162float(__float2bfloat16(c12));
                float r13 = c13 - __bfloat162float(__float2bfloat16(c13));
                pl[0] = pack_bf16x2(r00, r01);
                pl[1] = pack_bf16x2(r02, r03);
                pl[2] = pack_bf16x2(r10, r11);
                pl[3] = pack_bf16x2(r12, r13);
            }
            unsigned trow = (unsigned)(16 * t * KSTR) * 2u + ldsm_off;
#pragma unroll
            for (int nfp = 0; nfp < 8; nfp++) {
                unsigned vh0, vh1, vh2, vh3, vl0, vl1, vl2, vl3;
                unsigned coff = trow + (unsigned)(16 * nfp) * 2u;
                ldsm_x4_t(vh0, vh1, vh2, vh3, vh_s + coff);
                ldsm_x4_t(vl0, vl1, vl2, vl3, vl_s + coff);
                unsigned bh0[2] = {vh0, vh1}, bh1[2] = {vh2, vh3};
                unsigned bl0[2] = {vl0, vl1}, bl1[2] = {vl2, vl3};
                // interleave the two acc targets to break up dependent chains
                mma_bf16(acc[2 * nfp], ph, bh0);
                mma_bf16(acc[2 * nfp + 1], ph, bh1);
                mma_bf16(acc[2 * nfp], ph, bl0);
                mma_bf16(acc[2 * nfp + 1], ph, bl1);
                mma_bf16(acc[2 * nfp], pl, bh0);
                mma_bf16(acc[2 * nfp + 1], pl, bh1);
            }
        }
        __syncthreads();            // all warps done reading V[cur]
        if (nxt < NB) {
            FA_LOAD_V(nxt);         // prefetch V[nxt]
            CP_WAIT1();             // K[nxt] ready; V[nxt] stays in flight
            __syncthreads();
        }
        cur = nxt;
    }

    // epilogue: normalize + bf16 hi/lo split, write directly to GEMM input bufs
    float inv0 = 1.0f / l0, inv1 = 1.0f / l1;
    int r0 = qi * 64 + wr + g;
    size_t ob = (size_t)r0 * CCH + h * HD;
#pragma unroll
    for (int nf = 0; nf < 16; nf++) {
        int col = 8 * nf + tc2;
        float v0 = acc[nf][0] * inv0, v1 = acc[nf][1] * inv0;
        float v2 = acc[nf][2] * inv1, v3 = acc[nf][3] * inv1;
        __nv_bfloat16 b0 = __float2bfloat16(v0), b1 = __float2bfloat16(v1);
        __nv_bfloat16 b2 = __float2bfloat16(v2), b3 = __float2bfloat16(v3);
        float q0 = v0 - __bfloat162float(b0), q1 = v1 - __bfloat162float(b1);
        float q2 = v2 - __bfloat162float(b2), q3 = v3 - __bfloat162float(b3);
        *(unsigned*)&oh[ob + col] =
            ((unsigned)__bfloat16_as_ushort(b1) << 16) | __bfloat16_as_ushort(b0);
        *(unsigned*)&oh[ob + 8 * CCH + col] =
            ((unsigned)__bfloat16_as_ushort(b3) << 16) | __bfloat16_as_ushort(b2);
        *(unsigned*)&ol[ob + col] = pack_bf16x2(q0, q1);
        *(unsigned*)&ol[ob + 8 * CCH + col] = pack_bf16x2(q2, q3);
    }
}

// ---------------- launch ----------------------------------------------------------
extern "C" void kernel_launch(void* const* d_in, const int* in_sizes, int n_in,
                              void* d_out, int out_size)
{
    const float* x        = (const float*)d_in[0];
    const float* rope_cos = (const float*)d_in[1];
    const float* rope_sin = (const float*)d_in[2];
    const void*  sta      = (const void*)d_in[3];
    const float* Wq = (const float*)d_in[4];
    const float* bq = (const float*)d_in[5];
    const float* Wk = (const float*)d_in[6];
    const float* bk = (const float*)d_in[7];
    const float* Wv = (const float*)d_in[8];
    const float* bv = (const float*)d_in[9];
    const float* Wo = (const float*)d_in[10];
    const float* bo = (const float*)d_in[11];
    const float* qn_w = (const float*)d_in[12];
    const float* kn_w = (const float*)d_in[13];
    float* out = (float*)d_out;

    float *qp, *kp, *qbp, *kbp;
    unsigned char* mp;
    unsigned short *xh, *xl, *ah, *al;
    unsigned short *qsh, *qsl, *ksh, *ksl, *vsh, *vsl;
    unsigned short *wqh, *wql, *wkh, *wkl, *wvh, *wvl, *woh, *wol;
    cudaGetSymbolAddress((void**)&qp, g_q);
    cudaGetSymbolAddress((void**)&kp, g_k);
    cudaGetSymbolAddress((void**)&qbp, g_qb);
    cudaGetSymbolAddress((void**)&kbp, g_kb);
    cudaGetSymbolAddress((void**)&mp, g_mask);
    cudaGetSymbolAddress((void**)&xh, g_xh);
    cudaGetSymbolAddress((void**)&xl, g_xl);
    cudaGetSymbolAddress((void**)&ah, g_ah);
    cudaGetSymbolAddress((void**)&al, g_al);
    cudaGetSymbolAddress((void**)&qsh, g_qsh);
    cudaGetSymbolAddress((void**)&qsl, g_qsl);
    cudaGetSymbolAddress((void**)&ksh, g_ksh);
    cudaGetSymbolAddress((void**)&ksl, g_ksl);
    cudaGetSymbolAddress((void**)&vsh, g_vsh);
    cudaGetSymbolAddress((void**)&vsl, g_vsl);
    cudaGetSymbolAddress((void**)&wqh, g_wqh);
    cudaGetSymbolAddress((void**)&wql, g_wql);
    cudaGetSymbolAddress((void**)&wkh, g_wkh);
    cudaGetSymbolAddress((void**)&wkl, g_wkl);
    cudaGetSymbolAddress((void**)&wvh, g_wvh);
    cudaGetSymbolAddress((void**)&wvl, g_wvl);
    cudaGetSymbolAddress((void**)&woh, g_woh);
    cudaGetSymbolAddress((void**)&wol, g_wol);

    const int NEL = SQ * CCH;

    split_bf16<<<(NEL + 255) / 256, 256>>>(x, xh, xl, NEL);

    TransPtrs tp;
    tp.w[0] = Wq; tp.w[1] = Wk; tp.w[2] = Wv; tp.w[3] = Wo;
    tp.th[0] = wqh; tp.th[1] = wkh; tp.th[2] = wvh; tp.th[3] = woh;
    tp.tl[0] = wql; tp.tl[1] = wkl; tp.tl[2] = wvl; tp.tl[3] = wol;
    transpose_split4<<<dim3(CCH / 32, CCH / 32, 4), dim3(32, 32)>>>(tp);

    cudaFuncSetAttribute(gemm_tc, cudaFuncAttributeMaxDynamicSharedMemorySize, G2SMEM);
    cudaFuncSetAttribute(gemm_tc, cudaFuncAttributePreferredSharedMemoryCarveout, 100);
    dim3 ggrid(CCH / BN, SQ / BM);
    gemm_tc<<<ggrid, 256, G2SMEM>>>(xh, xl, wqh, wql, bq, qp, nullptr, nullptr);
    gemm_tc<<<ggrid, 256, G2SMEM>>>(xh, xl, wkh, wkl, bk, kp, nullptr, nullptr);
    gemm_tc<<<ggrid, 256, G2SMEM>>>(xh, xl, wvh, wvl, bv, nullptr, vsh, vsl);

    int nwarp_blocks = (SQ * NH) / 8;
    rmsnorm_rope_split<<<nwarp_blocks, 256>>>(qp, qn_w, rope_cos, rope_sin, qsh, qsl);
    rmsnorm_rope_split<<<nwarp_blocks, 256>>>(kp, kn_w, rope_cos, rope_sin, ksh, ksl);

    pool_blocks<<<dim3(NH, NB), 128>>>(qp, qbp);
    pool_blocks<<<dim3(NH, NB), 128>>>(kp, kbp);

    nabla_mask<<<dim3(NH, NB), 32>>>(qbp, kbp, sta, mp);

    cudaFuncSetAttribute(flash_attn_tc, cudaFuncAttributeMaxDynamicSharedMemorySize, FT_SMEM);
    flash_attn_tc<<<dim3(NB, NH), 128, FT_SMEM>>>(qsh, qsl, ksh, ksl, vsh, vsl, mp, ah, al);

    gemm_tc<<<ggrid, 256, G2SMEM>>>(ah, al, woh, wol, bo, out, nullptr, nullptr);
}

// round 14
// speedup vs baseline: 1.2981x; 1.2981x over previous
#include <cuda_runtime.h>
#include <cuda_bf16.h>
#include <cuda_fp16.h>
#include <math.h>

#define SQ   2048
#define CCH  2048
#define NH   16
#define HD   128
#define BLKS 64
#define NB   32
#define THRP 0.8f
#define EPSV 1e-6f

// ---------------- scratch (device globals; no allocation allowed) -------------
__device__ float g_q[SQ * CCH];
__device__ float g_k[SQ * CCH];
__device__ float g_qb[NH * NB * HD];
__device__ float g_kb[NH * NB * HD];
__device__ unsigned char g_mask[NH * NB * NB];

__device__ unsigned short g_xh[SQ * CCH];    // x bf16 hi (Q/K gemms)
__device__ unsigned short g_xl[SQ * CCH];    // x bf16 lo
__device__ unsigned short g_xfh[SQ * CCH];   // x fp16 hi (V gemm)
__device__ unsigned short g_xfl[SQ * CCH];   // x fp16 lo
__device__ unsigned short g_ah[SQ * CCH];    // attn out fp16 hi
__device__ unsigned short g_al[SQ * CCH];    // attn out fp16 lo
__device__ unsigned short g_qf[SQ * CCH];    // q fp16 (flash)
__device__ unsigned short g_kf[SQ * CCH];    // k fp16
__device__ unsigned short g_vf[SQ * CCH];    // v fp16
__device__ unsigned short g_wqh[CCH * CCH];  // bf16 hi/lo
__device__ unsigned short g_wql[CCH * CCH];
__device__ unsigned short g_wkh[CCH * CCH];
__device__ unsigned short g_wkl[CCH * CCH];
__device__ unsigned short g_wvh[CCH * CCH];  // fp16 hi only
__device__ unsigned short g_woh[CCH * CCH];  // fp16 hi only

// ================= helpers ======================================================
__device__ __forceinline__ unsigned pack_f16x2(float lo, float hi) {
    unsigned r;
    asm("cvt.rn.f16x2.f32 %0, %1, %2;" : "=r"(r) : "f"(hi), "f"(lo));
    return r;
}
__device__ __forceinline__ unsigned smem_u32(const void* p) {
    unsigned a;
    asm("{ .reg .u64 t; cvta.to.shared.u64 t, %1; cvt.u32.u64 %0, t; }" : "=r"(a) : "l"(p));
    return a;
}
__device__ __forceinline__ void mma_bf16(float* c, const unsigned* a, const unsigned* b)
{
    asm volatile(
        "mma.sync.aligned.m16n8k16.row.col.f32.bf16.bf16.f32 "
        "{%0,%1,%2,%3}, {%4,%5,%6,%7}, {%8,%9}, {%0,%1,%2,%3};"
        : "+f"(c[0]), "+f"(c[1]), "+f"(c[2]), "+f"(c[3])
        : "r"(a[0]), "r"(a[1]), "r"(a[2]), "r"(a[3]), "r"(b[0]), "r"(b[1]));
}
__device__ __forceinline__ void mma_f16(float* c, const unsigned* a, const unsigned* b)
{
    asm volatile(
        "mma.sync.aligned.m16n8k16.row.col.f32.f16.f16.f32 "
        "{%0,%1,%2,%3}, {%4,%5,%6,%7}, {%8,%9}, {%0,%1,%2,%3};"
        : "+f"(c[0]), "+f"(c[1]), "+f"(c[2]), "+f"(c[3])
        : "r"(a[0]), "r"(a[1]), "r"(a[2]), "r"(a[3]), "r"(b[0]), "r"(b[1]));
}
__device__ __forceinline__ void ldsm_x4(unsigned& r0, unsigned& r1, unsigned& r2, unsigned& r3,
                                        unsigned addr)
{
    asm volatile("ldmatrix.sync.aligned.m8n8.x4.shared.b16 {%0,%1,%2,%3}, [%4];"
                 : "=r"(r0), "=r"(r1), "=r"(r2), "=r"(r3) : "r"(addr));
}
__device__ __forceinline__ void ldsm_x4_t(unsigned& r0, unsigned& r1, unsigned& r2, unsigned& r3,
                                          unsigned addr)
{
    asm volatile("ldmatrix.sync.aligned.m8n8.x4.trans.shared.b16 {%0,%1,%2,%3}, [%4];"
                 : "=r"(r0), "=r"(r1), "=r"(r2), "=r"(r3) : "r"(addr));
}
__device__ __forceinline__ void cp16(unsigned sm, const void* g) {
    asm volatile("cp.async.cg.shared.global [%0], [%1], 16;" :: "r"(sm), "l"(g));
}
#define CP_COMMIT() asm volatile("cp.async.commit_group;" ::: "memory")
#define CP_WAIT0()  asm volatile("cp.async.wait_group 0;" ::: "memory")
#define CP_WAIT1()  asm volatile("cp.async.wait_group 1;" ::: "memory")

// ================= x split: bf16 hi/lo + fp16 hi/lo ============================
__global__ void split_x(const float* __restrict__ a,
                        unsigned short* __restrict__ bh, unsigned short* __restrict__ bl,
                        unsigned short* __restrict__ fh, unsigned short* __restrict__ fl, int n)
{
    int i = blockIdx.x * 256 + threadIdx.x;
    if (i < n) {
        float v = a[i];
        __nv_bfloat16 hb = __float2bfloat16(v);
        bh[i] = __bfloat16_as_ushort(hb);
        bl[i] = __bfloat16_as_ushort(__float2bfloat16(v - __bfloat162float(hb)));
        __half hf = __float2half_rn(v);
        fh[i] = __half_as_ushort(hf);
        fl[i] = __half_as_ushort(__float2half_rn(v - __half2float(hf)));
    }
}

// ================= transpose + split (4 weights; z<2 bf16 hi/lo, z>=2 fp16 hi) ==
struct TransPtrs {
    const float* w[4];
    unsigned short* th[4];
    unsigned short* tl[4];   // null for fp16 mode
};

__global__ void transpose_split4(TransPtrs P)
{
    __shared__ float t[32][33];
    int z = blockIdx.z;
    const float* W = P.w[z];
    unsigned short* Th = P.th[z];
    unsigned short* Tl = P.tl[z];
    int bx = blockIdx.x * 32, by = blockIdx.y * 32;
    int tx = threadIdx.x, ty = threadIdx.y;
    t[ty][tx] = W[(size_t)(by + ty) * CCH + bx + tx];
    __syncthreads();
    float v = t[tx][ty];
    size_t o = (size_t)(bx + ty) * CCH + by + tx;
    if (Tl != nullptr) {
        __nv_bfloat16 hi = __float2bfloat16(v);
        Th[o] = __bfloat16_as_ushort(hi);
        Tl[o] = __bfloat16_as_ushort(__float2bfloat16(v - __bfloat162float(hi)));
    } else {
        Th[o] = __half_as_ushort(__float2half_rn(v));
    }
}

// ================= bf16x3 GEMM (Q,K): 128x128 tile, cp.async 2-stage ============
#define BM 128
#define BN 128
#define BK 32
#define ASTR 40
#define TILE_U16 (128 * ASTR)
#define STAGE_U16 (4 * TILE_U16)
#define G2SMEM (2 * STAGE_U16 * 2)

__global__ __launch_bounds__(256, 2) void gemm_bf3(
    const unsigned short* __restrict__ Ah, const unsigned short* __restrict__ Al,
    const unsigned short* __restrict__ Bh, const unsigned short* __restrict__ Bl,
    const float* __restrict__ bias, float* __restrict__ Co)
{
    extern __shared__ __align__(16) unsigned short smg[];
    unsigned sbase = smem_u32(smg);

    int tid = threadIdx.x, w = tid >> 5, lane = tid & 31;
    int g = lane >> 2, tc2 = (lane & 3) * 2;
    int m0 = blockIdx.y * BM, n0 = blockIdx.x * BN;
    int wm = (w >> 2) * 64, wn = (w & 3) * 32;

    float acc[4][4][4];
#pragma unroll
    for (int i = 0; i < 4; i++)
#pragma unroll
        for (int j = 0; j < 4; j++)
#pragma unroll
            for (int l = 0; l < 4; l++) acc[i][j][l] = 0.f;

    int r0l = tid >> 2, c0l = (tid & 3) * 8;
    int r1l = (tid + 256) >> 2, c1l = ((tid + 256) & 3) * 8;

    unsigned aoffb = (unsigned)(((wm + (lane & 15)) * ASTR + ((lane >> 1) & 8)) * 2);
    unsigned boffb = (unsigned)(((wn + (lane & 7) + ((lane >> 1) & 8)) * ASTR + (lane & 8)) * 2);

    const int NCK = CCH / BK;

#define LOAD_STAGE(CK, SOFF)                                                        \
    {                                                                               \
        int kb = (CK) * BK;                                                         \
        unsigned s0 = sbase + (SOFF) + (unsigned)(r0l * ASTR + c0l) * 2u;           \
        unsigned s1 = sbase + (SOFF) + (unsigned)(r1l * ASTR + c1l) * 2u;           \
        size_t ga0 = (size_t)(m0 + r0l) * CCH + kb + c0l;                           \
        size_t ga1 = (size_t)(m0 + r1l) * CCH + kb + c1l;                           \
        size_t gb0 = (size_t)(n0 + r0l) * CCH + kb + c0l;                           \
        size_t gb1 = (size_t)(n0 + r1l) * CCH + kb + c1l;                           \
        cp16(s0, Ah + ga0);                                                         \
        cp16(s1, Ah + ga1);                                                         \
        cp16(s0 + TILE_U16 * 2u, Al + ga0);                                         \
        cp16(s1 + TILE_U16 * 2u, Al + ga1);                                         \
        cp16(s0 + 2u * TILE_U16 * 2u, Bh + gb0);                                    \
        cp16(s1 + 2u * TILE_U16 * 2u, Bh + gb1);                                    \
        cp16(s0 + 3u * TILE_U16 * 2u, Bl + gb0);                                    \
        cp16(s1 + 3u * TILE_U16 * 2u, Bl + gb1);                                    \
    }

    LOAD_STAGE(0, 0u);
    CP_COMMIT();

    for (int ck = 0; ck < NCK; ck++) {
        if (ck + 1 < NCK) {
            LOAD_STAGE(ck + 1, (unsigned)(((ck + 1) & 1) * STAGE_U16 * 2));
            CP_COMMIT();
            CP_WAIT1();
        } else {
            CP_WAIT0();
        }
        __syncthreads();

        unsigned stage = sbase + (unsigned)((ck & 1) * STAGE_U16 * 2);
        unsigned aH = stage + aoffb;
        unsigned bH = stage + 2u * TILE_U16 * 2u + boffb;

#pragma unroll
        for (int ks = 0; ks < BK; ks += 16) {
            unsigned ksb = (unsigned)(ks * 2);
            unsigned ah[4][4], al[4][4], bh[4][2], bl[4][2];
#pragma unroll
            for (int mf = 0; mf < 4; mf++) {
                unsigned ra = aH + (unsigned)(mf * 16 * ASTR * 2) + ksb;
                ldsm_x4(ah[mf][0], ah[mf][1], ah[mf][2], ah[mf][3], ra);
                ldsm_x4(al[mf][0], al[mf][1], al[mf][2], al[mf][3], ra + TILE_U16 * 2u);
            }
#pragma unroll
            for (int np = 0; np < 2; np++) {
                unsigned rb = bH + (unsigned)(np * 16 * ASTR * 2) + ksb;
                ldsm_x4(bh[2 * np][0], bh[2 * np][1], bh[2 * np + 1][0], bh[2 * np + 1][1], rb);
                ldsm_x4(bl[2 * np][0], bl[2 * np][1], bl[2 * np + 1][0], bl[2 * np + 1][1],
                        rb + TILE_U16 * 2u);
            }
#pragma unroll
            for (int mf = 0; mf < 4; mf++)
#pragma unroll
                for (int nf = 0; nf < 4; nf++)
                    mma_bf16(acc[mf][nf], ah[mf], bh[nf]);
#pragma unroll
            for (int mf = 0; mf < 4; mf++)
#pragma unroll
                for (int nf = 0; nf < 4; nf++)
                    mma_bf16(acc[mf][nf], ah[mf], bl[nf]);
#pragma unroll
            for (int mf = 0; mf < 4; mf++)
#pragma unroll
                for (int nf = 0; nf < 4; nf++)
                    mma_bf16(acc[mf][nf], al[mf], bh[nf]);
        }
        __syncthreads();
    }

#pragma unroll
    for (int mf = 0; mf < 4; mf++) {
        int r0 = m0 + wm + mf * 16 + g;
#pragma unroll
        for (int nf = 0; nf < 4; nf++) {
            int col = n0 + wn + nf * 8 + tc2;
            float bx = bias[col], by = bias[col + 1];
            float2 lo = make_float2(acc[mf][nf][0] + bx, acc[mf][nf][1] + by);
            float2 hi = make_float2(acc[mf][nf][2] + bx, acc[mf][nf][3] + by);
            *(float2*)(Co + (size_t)r0 * CCH + col) = lo;
            *(float2*)(Co + (size_t)(r0 + 8) * CCH + col) = hi;
        }
    }
}

// ================= fp16x2 GEMM (V, out): Ah·Bh + Al·Bh ==========================
#define F2STAGE_U16 (3 * TILE_U16)
#define F2SMEM (2 * F2STAGE_U16 * 2)

__global__ __launch_bounds__(256, 2) void gemm_f2(
    const unsigned short* __restrict__ Ah, const unsigned short* __restrict__ Al,
    const unsigned short* __restrict__ Bh,
    const float* __restrict__ bias, float* __restrict__ Co,
    unsigned short* __restrict__ OH)
{
    extern __shared__ __align__(16) unsigned short smg[];
    unsigned sbase = smem_u32(smg);

    int tid = threadIdx.x, w = tid >> 5, lane = tid & 31;
    int g = lane >> 2, tc2 = (lane & 3) * 2;
    int m0 = blockIdx.y * BM, n0 = blockIdx.x * BN;
    int wm = (w >> 2) * 64, wn = (w & 3) * 32;

    float acc[4][4][4];
#pragma unroll
    for (int i = 0; i < 4; i++)
#pragma unroll
        for (int j = 0; j < 4; j++)
#pragma unroll
            for (int l = 0; l < 4; l++) acc[i][j][l] = 0.f;

    int r0l = tid >> 2, c0l = (tid & 3) * 8;
    int r1l = (tid + 256) >> 2, c1l = ((tid + 256) & 3) * 8;

    unsigned aoffb = (unsigned)(((wm + (lane & 15)) * ASTR + ((lane >> 1) & 8)) * 2);
    unsigned boffb = (unsigned)(((wn + (lane & 7) + ((lane >> 1) & 8)) * ASTR + (lane & 8)) * 2);

    const int NCK = CCH / BK;

#define F2_LOAD(CK, SOFF)                                                           \
    {                                                                               \
        int kb = (CK) * BK;                                                         \
        unsigned s0 = sbase + (SOFF) + (unsigned)(r0l * ASTR + c0l) * 2u;           \
        unsigned s1 = sbase + (SOFF) + (unsigned)(r1l * ASTR + c1l) * 2u;           \
        size_t ga0 = (size_t)(m0 + r0l) * CCH + kb + c0l;                           \
        size_t ga1 = (size_t)(m0 + r1l) * CCH + kb + c1l;                           \
        size_t gb0 = (size_t)(n0 + r0l) * CCH + kb + c0l;                           \
        size_t gb1 = (size_t)(n0 + r1l) * CCH + kb + c1l;                           \
        cp16(s0, Ah + ga0);                                                         \
        cp16(s1, Ah + ga1);                                                         \
        cp16(s0 + TILE_U16 * 2u, Al + ga0);                                         \
        cp16(s1 + TILE_U16 * 2u, Al + ga1);                                         \
        cp16(s0 + 2u * TILE_U16 * 2u, Bh + gb0);                                    \
        cp16(s1 + 2u * TILE_U16 * 2u, Bh + gb1);                                    \
    }

    F2_LOAD(0, 0u);
    CP_COMMIT();

    for (int ck = 0; ck < NCK; ck++) {
        if (ck + 1 < NCK) {
            F2_LOAD(ck + 1, (unsigned)(((ck + 1) & 1) * F2STAGE_U16 * 2));
            CP_COMMIT();
            CP_WAIT1();
        } else {
            CP_WAIT0();
        }
        __syncthreads();

        unsigned stage = sbase + (unsigned)((ck & 1) * F2STAGE_U16 * 2);
        unsigned aH = stage + aoffb;
        unsigned bH = stage + 2u * TILE_U16 * 2u + boffb;

#pragma unroll
        for (int ks = 0; ks < BK; ks += 16) {
            unsigned ksb = (unsigned)(ks * 2);
            unsigned ah[4][4], al[4][4], bh[4][2];
#pragma unroll
            for (int mf = 0; mf < 4; mf++) {
                unsigned ra = aH + (unsigned)(mf * 16 * ASTR * 2) + ksb;
                ldsm_x4(ah[mf][0], ah[mf][1], ah[mf][2], ah[mf][3], ra);
                ldsm_x4(al[mf][0], al[mf][1], al[mf][2], al[mf][3], ra + TILE_U16 * 2u);
            }
#pragma unroll
            for (int np = 0; np < 2; np++) {
                unsigned rb = bH + (unsigned)(np * 16 * ASTR * 2) + ksb;
                ldsm_x4(bh[2 * np][0], bh[2 * np][1], bh[2 * np + 1][0], bh[2 * np + 1][1], rb);
            }
#pragma unroll
            for (int mf = 0; mf < 4; mf++)
#pragma unroll
                for (int nf = 0; nf < 4; nf++)
                    mma_f16(acc[mf][nf], ah[mf], bh[nf]);
#pragma unroll
            for (int mf = 0; mf < 4; mf++)
#pragma unroll
                for (int nf = 0; nf < 4; nf++)
                    mma_f16(acc[mf][nf], al[mf], bh[nf]);
        }
        __syncthreads();
    }

    if (OH == nullptr) {
#pragma unroll
        for (int mf = 0; mf < 4; mf++) {
            int r0 = m0 + wm + mf * 16 + g;
#pragma unroll
            for (int nf = 0; nf < 4; nf++) {
                int col = n0 + wn + nf * 8 + tc2;
                float bx = bias[col], by = bias[col + 1];
                float2 lo = make_float2(acc[mf][nf][0] + bx, acc[mf][nf][1] + by);
                float2 hi = make_float2(acc[mf][nf][2] + bx, acc[mf][nf][3] + by);
                *(float2*)(Co + (size_t)r0 * CCH + col) = lo;
                *(float2*)(Co + (size_t)(r0 + 8) * CCH + col) = hi;
            }
        }
    } else {
        // fp16 single output (+bias) for flash V input
#pragma unroll
        for (int mf = 0; mf < 4; mf++) {
            int r0 = m0 + wm + mf * 16 + g;
#pragma unroll
            for (int nf = 0; nf < 4; nf++) {
                int col = n0 + wn + nf * 8 + tc2;
                float bx = bias[col], by = bias[col + 1];
                float v0 = acc[mf][nf][0] + bx, v1 = acc[mf][nf][1] + by;
                float v2 = acc[mf][nf][2] + bx, v3 = acc[mf][nf][3] + by;
                *(unsigned*)&OH[(size_t)r0 * CCH + col] = pack_f16x2(v0, v1);
                *(unsigned*)&OH[(size_t)(r0 + 8) * CCH + col] = pack_f16x2(v2, v3);
            }
        }
    }
}

// ---------------- fused RMSNorm + RoPE + fp16 store, in-place -------------------
__global__ __launch_bounds__(256) void rmsnorm_rope_f16(
    float* __restrict__ buf, const float* __restrict__ w,
    const float* __restrict__ cs, const float* __restrict__ sn,
    unsigned short* __restrict__ oh)
{
    int warp = (blockIdx.x * blockDim.x + threadIdx.x) >> 5;
    int lane = threadIdx.x & 31;
    if (warp >= SQ * NH) return;
    int s = warp / NH, h = warp % NH;
    size_t base = (size_t)s * CCH + h * HD;
    float* row = buf + base;

    float x0 = row[lane], x1 = row[lane + 32], x2 = row[lane + 64], x3 = row[lane + 96];
    float ss = x0 * x0 + x1 * x1 + x2 * x2 + x3 * x3;
#pragma unroll
    for (int o = 16; o; o >>= 1) ss += __shfl_xor_sync(0xffffffffu, ss, o);
    float r = rsqrtf(ss * (1.0f / HD) + EPSV);

    float y0 = x0 * r * w[lane];
    float y1 = x1 * r * w[lane + 32];
    float y2 = x2 * r * w[lane + 64];
    float y3 = x3 * r * w[lane + 96];

    const float* cr = cs + (size_t)s * HD;
    const float* sr = sn + (size_t)s * HD;
    float z0 = y0 * cr[lane]      - y2 * sr[lane];
    float z1 = y1 * cr[lane + 32] - y3 * sr[lane + 32];
    float z2 = y2 * cr[lane + 64] + y0 * sr[lane + 64];
    float z3 = y3 * cr[lane + 96] + y1 * sr[lane + 96];

    row[lane] = z0; row[lane + 32] = z1; row[lane + 64] = z2; row[lane + 96] = z3;

    oh[base + lane]      = __half_as_ushort(__float2half_rn(z0));
    oh[base + lane + 32] = __half_as_ushort(__float2half_rn(z1));
    oh[base + lane + 64] = __half_as_ushort(__float2half_rn(z2));
    oh[base + lane + 96] = __half_as_ushort(__float2half_rn(z3));
}

// ---------------- block pooling ------------------------------------------------
__global__ void pool_blocks(const float* __restrict__ buf, float* __restrict__ out)
{
    int h = blockIdx.x, b = blockIdx.y, d = threadIdx.x;
    float sum = 0.f;
#pragma unroll 8
    for (int i = 0; i < BLKS; i++)
        sum += buf[(size_t)(b * BLKS + i) * CCH + h * HD + d];
    out[((h * NB) + b) * HD + d] = sum * (1.0f / BLKS);
}

// ---------------- NABLA block mask ----------------------------------------------
__device__ __forceinline__ int sniff_sta_dtype(const unsigned int* w)
{
    bool all01 = true, allf = true;
    for (int i = 0; i < 256; i++) {
        unsigned int v = w[i];
        if (v > 1u) all01 = false;
        if (v != 0u && v != 0x3F800000u) allf = false;
    }
    if (all01) return 0;
    if (allf) return 1;
    return 2;
}

__global__ void nabla_mask(const float* __restrict__ qb, const float* __restrict__ kb,
                           const void* __restrict__ sta, unsigned char* __restrict__ mask)
{
    int h = blockIdx.x, q = blockIdx.y, k = threadIdx.x;
    __shared__ float p[NB];
    __shared__ float cutoff;
    __shared__ int sdt;
    if (k == 0) sdt = sniff_sta_dtype((const unsigned int*)sta);

    const float* qr = qb + (h * NB + q) * HD;
    const float* kr = kb + (h * NB + k) * HD;
    float dot = 0.f;
#pragma unroll 16
    for (int d = 0; d < HD; d++) dot += qr[d] * kr[d];
    p[k] = dot * 0.08838834764831845f;
    __syncthreads();
    if (k == 0) {
        float mx = -1e30f;
        for (int i = 0; i < NB; i++) mx = fmaxf(mx, p[i]);
        float sum = 0.f;
        for (int i = 0; i < NB; i++) { p[i] = expf(p[i] - mx); sum += p[i]; }
        float inv = 1.0f / sum;
        float srt[NB];
        for (int i = 0; i < NB; i++) { p[i] *= inv; srt[i] = p[i]; }
        for (int i = 1; i < NB; i++) {
            float v = srt[i];
            int j = i - 1;
            while (j >= 0 && srt[j] < v) { srt[j + 1] = srt[j]; j--; }
            srt[j + 1] = v;
        }
        float run = 0.f, co = 1e30f;
        for (int i = 0; i < NB; i++) {
            if (run < THRP) { co = srt[i]; run += srt[i]; }
        }
        cutoff = co;
    }
    __syncthreads();

    bool sta_on;
    int sidx = q * NB + k;
    if (sdt == 0)      sta_on = ((const int*)sta)[sidx] != 0;
    else if (sdt == 1) sta_on = ((const float*)sta)[sidx] != 0.0f;
    else               sta_on = ((const unsigned char*)sta)[sidx] != 0;

    unsigned char keep = (p[k] >= cutoff) || sta_on;
    mask[(h * NB + q) * NB + k] = keep;
}

// ---------------- fp16 single-pass flash attention (double-buffered K+V) --------
#define KSTR 136
#define BUF_U16 (64 * KSTR)
#define FF_SMEM (4 * BUF_U16 * 2)   // K0,V0,K1,V1

__global__ __launch_bounds__(128) void flash_f16(
    const unsigned short* __restrict__ qf, const unsigned short* __restrict__ kf,
    const unsigned short* __restrict__ vf, const unsigned char* __restrict__ mask,
    unsigned short* __restrict__ oh, unsigned short* __restrict__ ol)
{
    extern __shared__ __align__(16) unsigned short smu[];

    int qi = blockIdx.x, h = blockIdx.y;
    int tid = threadIdx.x, w = tid >> 5, lane = tid & 31;
    int g = lane >> 2, tc2 = (lane & 3) * 2;
    int wr = w * 16;

    // stage Q (fp16 single) into buffer 0, extract register fragments
    for (int idx = tid; idx < 64 * 16; idx += 128) {
        int r = idx >> 4, c = (idx & 15) * 8;
        size_t off = (size_t)(qi * 64 + r) * CCH + h * HD + c;
        *(uint4*)&smu[r * KSTR + c] = *(const uint4*)(qf + off);
    }
    __syncthreads();

    unsigned qfr[8][4];
#pragma unroll
    for (int t = 0; t < 8; t++) {
        int r0 = (wr + g) * KSTR + 16 * t + tc2;
        int r8 = (wr + 8 + g) * KSTR + 16 * t + tc2;
        qfr[t][0] = *(const unsigned*)&smu[r0];
        qfr[t][1] = *(const unsigned*)&smu[r8];
        qfr[t][2] = *(const unsigned*)&smu[r0 + 8];
        qfr[t][3] = *(const unsigned*)&smu[r8 + 8];
    }
    __syncthreads();

    float acc[16][4];
#pragma unroll
    for (int nf = 0; nf < 16; nf++)
#pragma unroll
        for (int i = 0; i < 4; i++) acc[nf][i] = 0.f;
    float m0 = -1e30f, m1 = -1e30f, l0 = 0.f, l1 = 0.f;

    const unsigned char* mrowp = mask + (h * NB + qi) * NB;
    const float scl = 0.08838834764831845f;
    unsigned base_s = smem_u32(smu);
    int lj = lane >> 3, li = lane & 7;
    unsigned ldsm_off = (unsigned)(((lj & 1) * 8 + li) * KSTR + (lj >> 1) * 8) * 2u;

    // buffer b: K at b*2*BUF_U16, V at b*2*BUF_U16 + BUF_U16
#define FF_LOAD(B, BUF)                                                              \
    {                                                                                \
        unsigned kb_s = base_s + (unsigned)((BUF) * 2 * BUF_U16) * 2u;               \
        unsigned vb_s = kb_s + (unsigned)BUF_U16 * 2u;                               \
        _Pragma("unroll")                                                            \
        for (int it = 0; it < 8; it++) {                                             \
            int idx = tid + it * 128;                                                \
            int r = idx >> 4, c = (idx & 15) * 8;                                    \
            size_t off = (size_t)((B) * 64 + r) * CCH + h * HD + c;                  \
            unsigned so = (unsigned)((r * KSTR + c) * 2);                            \
            cp16(kb_s + so, kf + off);                                               \
            cp16(vb_s + so, vf + off);                                               \
        }                                                                            \
        CP_COMMIT();                                                                 \
    }

    int cur = 0;
    while (cur < NB && !mrowp[cur]) cur++;
    int p = 0;
    if (cur < NB) {
        FF_LOAD(cur, 0);
        CP_WAIT0();
        __syncthreads();
    }

    while (cur < NB) {
        int nxt = cur + 1;
        while (nxt < NB && !mrowp[nxt]) nxt++;
        if (nxt < NB) FF_LOAD(nxt, p ^ 1);   // prefetch both K,V of next block

        const unsigned short* Kc = smu + p * 2 * BUF_U16;
        unsigned v_s = base_s + (unsigned)(p * 2 * BUF_U16 + BUF_U16) * 2u;

        // ---- S = Q K^T (single pass), t-outer for independence ---------------------
        float sc[8][4];
#pragma unroll
        for (int j = 0; j < 8; j++)
#pragma unroll
            for (int i = 0; i < 4; i++) sc[j][i] = 0.f;

#pragma unroll
        for (int t = 0; t < 8; t++) {
#pragma unroll
            for (int j = 0; j < 8; j++) {
                int rbase = (8 * j + g) * KSTR + 16 * t;
                unsigned bh[2];
                bh[0] = *(const unsigned*)&Kc[rbase + tc2];
                bh[1] = *(const unsigned*)&Kc[rbase + 8 + tc2];
                mma_f16(sc[j], qfr[t], bh);
            }
        }

        // ---- online softmax ---------------------------------------------------------
        float rm0 = -1e30f, rm1 = -1e30f;
#pragma unroll
        for (int j = 0; j < 8; j++) {
#pragma unroll
            for (int i = 0; i < 4; i++) sc[j][i] *= scl;
            rm0 = fmaxf(rm0, fmaxf(sc[j][0], sc[j][1]));
            rm1 = fmaxf(rm1, fmaxf(sc[j][2], sc[j][3]));
        }
        rm0 = fmaxf(rm0, __shfl_xor_sync(0xffffffffu, rm0, 1));
        rm0 = fmaxf(rm0, __shfl_xor_sync(0xffffffffu, rm0, 2));
        rm1 = fmaxf(rm1, __shfl_xor_sync(0xffffffffu, rm1, 1));
        rm1 = fmaxf(rm1, __shfl_xor_sync(0xffffffffu, rm1, 2));
        float mn0 = fmaxf(m0, rm0), mn1 = fmaxf(m1, rm1);
        float es0 = __expf(m0 - mn0), es1 = __expf(m1 - mn1);

        float rs0 = 0.f, rs1 = 0.f;
#pragma unroll
        for (int j = 0; j < 8; j++) {
            sc[j][0] = __expf(sc[j][0] - mn0);
            sc[j][1] = __expf(sc[j][1] - mn0);
            sc[j][2] = __expf(sc[j][2] - mn1);
            sc[j][3] = __expf(sc[j][3] - mn1);
            rs0 += sc[j][0] + sc[j][1];
            rs1 += sc[j][2] + sc[j][3];
        }
        rs0 += __shfl_xor_sync(0xffffffffu, rs0, 1);
        rs0 += __shfl_xor_sync(0xffffffffu, rs0, 2);
        rs1 += __shfl_xor_sync(0xffffffffu, rs1, 1);
        rs1 += __shfl_xor_sync(0xffffffffu, rs1, 2);
        l0 = l0 * es0 + rs0;
        l1 = l1 * es1 + rs1;
        m0 = mn0; m1 = mn1;
#pragma unroll
        for (int nf = 0; nf < 16; nf++) {
            acc[nf][0] *= es0; acc[nf][1] *= es0;
            acc[nf][2] *= es1; acc[nf][3] *= es1;
        }

        // ---- O += P V (single pass, fp16 P) -----------------------------------------
#pragma unroll
        for (int t = 0; t < 4; t++) {
            unsigned ph[4];
            ph[0] = pack_f16x2(sc[2 * t][0], sc[2 * t][1]);
            ph[1] = pack_f16x2(sc[2 * t][2], sc[2 * t][3]);
            ph[2] = pack_f16x2(sc[2 * t + 1][0], sc[2 * t + 1][1]);
            ph[3] = pack_f16x2(sc[2 * t + 1][2], sc[2 * t + 1][3]);
            unsigned trow = (unsigned)(16 * t * KSTR) * 2u + ldsm_off;
#pragma unroll
            for (int nfp = 0; nfp < 8; nfp++) {
                unsigned v0r, v1r, v2r, v3r;
                ldsm_x4_t(v0r, v1r, v2r, v3r, v_s + trow + (unsigned)(16 * nfp) * 2u);
                unsigned bh0[2] = {v0r, v1r}, bh1[2] = {v2r, v3r};
                mma_f16(acc[2 * nfp], ph, bh0);
                mma_f16(acc[2 * nfp + 1], ph, bh1);
            }
        }

        if (nxt < NB) CP_WAIT0();
        __syncthreads();
        p ^= 1;
        cur = nxt;
    }

    // epilogue: normalize + fp16 hi/lo split for out-proj
    float inv0 = 1.0f / l0, inv1 = 1.0f / l1;
    int r0 = qi * 64 + wr + g;
    size_t ob = (size_t)r0 * CCH + h * HD;
#pragma unroll
    for (int nf = 0; nf < 16; nf++) {
        int col = 8 * nf + tc2;
        float v0 = acc[nf][0] * inv0, v1 = acc[nf][1] * inv0;
        float v2 = acc[nf][2] * inv1, v3 = acc[nf][3] * inv1;
        __half h0 = __float2half_rn(v0), h1 = __float2half_rn(v1);
        __half h2 = __float2half_rn(v2), h3 = __float2half_rn(v3);
        float q0 = v0 - __half2float(h0), q1 = v1 - __half2float(h1);
        float q2 = v2 - __half2float(h2), q3 = v3 - __half2float(h3);
        *(unsigned*)&oh[ob + col] =
            ((unsigned)__half_as_ushort(h1) << 16) | __half_as_ushort(h0);
        *(unsigned*)&oh[ob + 8 * CCH + col] =
            ((unsigned)__half_as_ushort(h3) << 16) | __half_as_ushort(h2);
        *(unsigned*)&ol[ob + col] = pack_f16x2(q0, q1);
        *(unsigned*)&ol[ob + 8 * CCH + col] = pack_f16x2(q2, q3);
    }
}

// ---------------- launch ----------------------------------------------------------
extern "C" void kernel_launch(void* const* d_in, const int* in_sizes, int n_in,
                              void* d_out, int out_size)
{
    const float* x        = (const float*)d_in[0];
    const float* rope_cos = (const float*)d_in[1];
    const float* rope_sin = (const float*)d_in[2];
    const void*  sta      = (const void*)d_in[3];
    const float* Wq = (const float*)d_in[4];
    const float* bq = (const float*)d_in[5];
    const float* Wk = (const float*)d_in[6];
    const float* bk = (const float*)d_in[7];
    const float* Wv = (const float*)d_in[8];
    const float* bv = (const float*)d_in[9];
    const float* Wo = (const float*)d_in[10];
    const float* bo = (const float*)d_in[11];
    const float* qn_w = (const float*)d_in[12];
    const float* kn_w = (const float*)d_in[13];
    float* out = (float*)d_out;

    float *qp, *kp, *qbp, *kbp;
    unsigned char* mp;
    unsigned short *xh, *xl, *xfh, *xfl, *ah, *al, *qfp, *kfp, *vfp;
    unsigned short *wqh, *wql, *wkh, *wkl, *wvh, *woh;
    cudaGetSymbolAddress((void**)&qp, g_q);
    cudaGetSymbolAddress((void**)&kp, g_k);
    cudaGetSymbolAddress((void**)&qbp, g_qb);
    cudaGetSymbolAddress((void**)&kbp, g_kb);
    cudaGetSymbolAddress((void**)&mp, g_mask);
    cudaGetSymbolAddress((void**)&xh, g_xh);
    cudaGetSymbolAddress((void**)&xl, g_xl);
    cudaGetSymbolAddress((void**)&xfh, g_xfh);
    cudaGetSymbolAddress((void**)&xfl, g_xfl);
    cudaGetSymbolAddress((void**)&ah, g_ah);
    cudaGetSymbolAddress((void**)&al, g_al);
    cudaGetSymbolAddress((void**)&qfp, g_qf);
    cudaGetSymbolAddress((void**)&kfp, g_kf);
    cudaGetSymbolAddress((void**)&vfp, g_vf);
    cudaGetSymbolAddress((void**)&wqh, g_wqh);
    cudaGetSymbolAddress((void**)&wql, g_wql);
    cudaGetSymbolAddress((void**)&wkh, g_wkh);
    cudaGetSymbolAddress((void**)&wkl, g_wkl);
    cudaGetSymbolAddress((void**)&wvh, g_wvh);
    cudaGetSymbolAddress((void**)&woh, g_woh);

    const int NEL = SQ * CCH;

    split_x<<<(NEL + 255) / 256, 256>>>(x, xh, xl, xfh, xfl, NEL);

    TransPtrs tp;
    tp.w[0] = Wq; tp.w[1] = Wk; tp.w[2] = Wv; tp.w[3] = Wo;
    tp.th[0] = wqh; tp.th[1] = wkh; tp.th[2] = wvh; tp.th[3] = woh;
    tp.tl[0] = wql; tp.tl[1] = wkl; tp.tl[2] = nullptr; tp.tl[3] = nullptr;
    transpose_split4<<<dim3(CCH / 32, CCH / 32, 4), dim3(32, 32)>>>(tp);

    cudaFuncSetAttribute(gemm_bf3, cudaFuncAttributeMaxDynamicSharedMemorySize, G2SMEM);
    cudaFuncSetAttribute(gemm_f2, cudaFuncAttributeMaxDynamicSharedMemorySize, F2SMEM);
    dim3 ggrid(CCH / BN, SQ / BM);
    gemm_bf3<<<ggrid, 256, G2SMEM>>>(xh, xl, wqh, wql, bq, qp);
    gemm_bf3<<<ggrid, 256, G2SMEM>>>(xh, xl, wkh, wkl, bk, kp);
    gemm_f2<<<ggrid, 256, F2SMEM>>>(xfh, xfl, wvh, bv, nullptr, vfp);

    int nwarp_blocks = (SQ * NH) / 8;
    rmsnorm_rope_f16<<<nwarp_blocks, 256>>>(qp, qn_w, rope_cos, rope_sin, qfp);
    rmsnorm_rope_f16<<<nwarp_blocks, 256>>>(kp, kn_w, rope_cos, rope_sin, kfp);

    pool_blocks<<<dim3(NH, NB), 128>>>(qp, qbp);
    pool_blocks<<<dim3(NH, NB), 128>>>(kp, kbp);

    nabla_mask<<<dim3(NH, NB), 32>>>(qbp, kbp, sta, mp);

    cudaFuncSetAttribute(flash_f16, cudaFuncAttributeMaxDynamicSharedMemorySize, FF_SMEM);
    flash_f16<<<dim3(NB, NH), 128, FF_SMEM>>>(qfp, kfp, vfp, mp, ah, al);

    gemm_f2<<<ggrid, 256, F2SMEM>>>(ah, al, woh, bo, out, nullptr);
}

// round 15
// speedup vs baseline: 1.4432x; 1.1118x over previous
#include <cuda_runtime.h>
#include <cuda_bf16.h>
#include <cuda_fp16.h>
#include <math.h>

#define SQ   2048
#define CCH  2048
#define NH   16
#define HD   128
#define BLKS 64
#define NB   32
#define THRP 0.8f
#define EPSV 1e-6f

// ---------------- scratch (device globals; no allocation allowed) -------------
__device__ float g_q[SQ * CCH];
__device__ float g_k[SQ * CCH];
__device__ float g_qb[NH * NB * HD];
__device__ float g_kb[NH * NB * HD];
__device__ unsigned char g_mask[NH * NB * NB];

__device__ unsigned short g_xh[SQ * CCH];    // x bf16 hi (Q/K gemms)
__device__ unsigned short g_xl[SQ * CCH];    // x bf16 lo
__device__ unsigned short g_xf[SQ * CCH];    // x fp16 (V gemm, single)
__device__ unsigned short g_af[SQ * CCH];    // attn out fp16 (out gemm, single)
__device__ unsigned short g_qf[SQ * CCH];    // q fp16 (flash)
__device__ unsigned short g_kf[SQ * CCH];    // k fp16
__device__ unsigned short g_vf[SQ * CCH];    // v fp16
__device__ unsigned short g_wqh[CCH * CCH];  // bf16 hi/lo
__device__ unsigned short g_wql[CCH * CCH];
__device__ unsigned short g_wkh[CCH * CCH];
__device__ unsigned short g_wkl[CCH * CCH];
__device__ unsigned short g_wvh[CCH * CCH];  // fp16 single
__device__ unsigned short g_woh[CCH * CCH];  // fp16 single

// ================= helpers ======================================================
__device__ __forceinline__ unsigned pack_f16x2(float lo, float hi) {
    unsigned r;
    asm("cvt.rn.f16x2.f32 %0, %1, %2;" : "=r"(r) : "f"(hi), "f"(lo));
    return r;
}
__device__ __forceinline__ unsigned smem_u32(const void* p) {
    unsigned a;
    asm("{ .reg .u64 t; cvta.to.shared.u64 t, %1; cvt.u32.u64 %0, t; }" : "=r"(a) : "l"(p));
    return a;
}
__device__ __forceinline__ void mma_bf16(float* c, const unsigned* a, const unsigned* b)
{
    asm volatile(
        "mma.sync.aligned.m16n8k16.row.col.f32.bf16.bf16.f32 "
        "{%0,%1,%2,%3}, {%4,%5,%6,%7}, {%8,%9}, {%0,%1,%2,%3};"
        : "+f"(c[0]), "+f"(c[1]), "+f"(c[2]), "+f"(c[3])
        : "r"(a[0]), "r"(a[1]), "r"(a[2]), "r"(a[3]), "r"(b[0]), "r"(b[1]));
}
__device__ __forceinline__ void mma_f16(float* c, const unsigned* a, const unsigned* b)
{
    asm volatile(
        "mma.sync.aligned.m16n8k16.row.col.f32.f16.f16.f32 "
        "{%0,%1,%2,%3}, {%4,%5,%6,%7}, {%8,%9}, {%0,%1,%2,%3};"
        : "+f"(c[0]), "+f"(c[1]), "+f"(c[2]), "+f"(c[3])
        : "r"(a[0]), "r"(a[1]), "r"(a[2]), "r"(a[3]), "r"(b[0]), "r"(b[1]));
}
__device__ __forceinline__ void ldsm_x4(unsigned& r0, unsigned& r1, unsigned& r2, unsigned& r3,
                                        unsigned addr)
{
    asm volatile("ldmatrix.sync.aligned.m8n8.x4.shared.b16 {%0,%1,%2,%3}, [%4];"
                 : "=r"(r0), "=r"(r1), "=r"(r2), "=r"(r3) : "r"(addr));
}
__device__ __forceinline__ void ldsm_x4_t(unsigned& r0, unsigned& r1, unsigned& r2, unsigned& r3,
                                          unsigned addr)
{
    asm volatile("ldmatrix.sync.aligned.m8n8.x4.trans.shared.b16 {%0,%1,%2,%3}, [%4];"
                 : "=r"(r0), "=r"(r1), "=r"(r2), "=r"(r3) : "r"(addr));
}
__device__ __forceinline__ void cp16(unsigned sm, const void* g) {
    asm volatile("cp.async.cg.shared.global [%0], [%1], 16;" :: "r"(sm), "l"(g));
}
#define CP_COMMIT() asm volatile("cp.async.commit_group;" ::: "memory")
#define CP_WAIT0()  asm volatile("cp.async.wait_group 0;" ::: "memory")
#define CP_WAIT1()  asm volatile("cp.async.wait_group 1;" ::: "memory")

// ================= x split: bf16 hi/lo + fp16 single ===========================
__global__ void split_x(const float* __restrict__ a,
                        unsigned short* __restrict__ bh, unsigned short* __restrict__ bl,
                        unsigned short* __restrict__ fh, int n)
{
    int i = blockIdx.x * 256 + threadIdx.x;
    if (i < n) {
        float v = a[i];
        __nv_bfloat16 hb = __float2bfloat16(v);
        bh[i] = __bfloat16_as_ushort(hb);
        bl[i] = __bfloat16_as_ushort(__float2bfloat16(v - __bfloat162float(hb)));
        fh[i] = __half_as_ushort(__float2half_rn(v));
    }
}

// ================= transpose + split (4 weights; z<2 bf16 hi/lo, z>=2 fp16) =====
struct TransPtrs {
    const float* w[4];
    unsigned short* th[4];
    unsigned short* tl[4];   // null for fp16 mode
};

__global__ void transpose_split4(TransPtrs P)
{
    __shared__ float t[32][33];
    int z = blockIdx.z;
    const float* W = P.w[z];
    unsigned short* Th = P.th[z];
    unsigned short* Tl = P.tl[z];
    int bx = blockIdx.x * 32, by = blockIdx.y * 32;
    int tx = threadIdx.x, ty = threadIdx.y;
    t[ty][tx] = W[(size_t)(by + ty) * CCH + bx + tx];
    __syncthreads();
    float v = t[tx][ty];
    size_t o = (size_t)(bx + ty) * CCH + by + tx;
    if (Tl != nullptr) {
        __nv_bfloat16 hi = __float2bfloat16(v);
        Th[o] = __bfloat16_as_ushort(hi);
        Tl[o] = __bfloat16_as_ushort(__float2bfloat16(v - __bfloat162float(hi)));
    } else {
        Th[o] = __half_as_ushort(__float2half_rn(v));
    }
}

// ================= bf16x3 GEMM (Q+K z-merged): 128x128, cp.async 2-stage ========
#define BM 128
#define BN 128
#define BK 32
#define ASTR 40
#define TILE_U16 (128 * ASTR)
#define STAGE_U16 (4 * TILE_U16)
#define G2SMEM (2 * STAGE_U16 * 2)

struct Gemm2 {
    const unsigned short* bh[2];
    const unsigned short* bl[2];
    const float* bias[2];
    float* out[2];
};

__global__ __launch_bounds__(256, 2) void gemm_bf3(
    const unsigned short* __restrict__ Ah, const unsigned short* __restrict__ Al, Gemm2 P)
{
    extern __shared__ __align__(16) unsigned short smg[];
    unsigned sbase = smem_u32(smg);

    int z = blockIdx.z;
    const unsigned short* __restrict__ Bh = P.bh[z];
    const unsigned short* __restrict__ Bl = P.bl[z];
    const float* __restrict__ bias = P.bias[z];
    float* __restrict__ Co = P.out[z];

    int tid = threadIdx.x, w = tid >> 5, lane = tid & 31;
    int g = lane >> 2, tc2 = (lane & 3) * 2;
    int m0 = blockIdx.y * BM, n0 = blockIdx.x * BN;
    int wm = (w >> 2) * 64, wn = (w & 3) * 32;

    float acc[4][4][4];
#pragma unroll
    for (int i = 0; i < 4; i++)
#pragma unroll
        for (int j = 0; j < 4; j++)
#pragma unroll
            for (int l = 0; l < 4; l++) acc[i][j][l] = 0.f;

    int r0l = tid >> 2, c0l = (tid & 3) * 8;
    int r1l = (tid + 256) >> 2, c1l = ((tid + 256) & 3) * 8;

    unsigned aoffb = (unsigned)(((wm + (lane & 15)) * ASTR + ((lane >> 1) & 8)) * 2);
    unsigned boffb = (unsigned)(((wn + (lane & 7) + ((lane >> 1) & 8)) * ASTR + (lane & 8)) * 2);

    const int NCK = CCH / BK;

#define LOAD_STAGE(CK, SOFF)                                                        \
    {                                                                               \
        int kb = (CK) * BK;                                                         \
        unsigned s0 = sbase + (SOFF) + (unsigned)(r0l * ASTR + c0l) * 2u;           \
        unsigned s1 = sbase + (SOFF) + (unsigned)(r1l * ASTR + c1l) * 2u;           \
        size_t ga0 = (size_t)(m0 + r0l) * CCH + kb + c0l;                           \
        size_t ga1 = (size_t)(m0 + r1l) * CCH + kb + c1l;                           \
        size_t gb0 = (size_t)(n0 + r0l) * CCH + kb + c0l;                           \
        size_t gb1 = (size_t)(n0 + r1l) * CCH + kb + c1l;                           \
        cp16(s0, Ah + ga0);                                                         \
        cp16(s1, Ah + ga1);                                                         \
        cp16(s0 + TILE_U16 * 2u, Al + ga0);                                         \
        cp16(s1 + TILE_U16 * 2u, Al + ga1);                                         \
        cp16(s0 + 2u * TILE_U16 * 2u, Bh + gb0);                                    \
        cp16(s1 + 2u * TILE_U16 * 2u, Bh + gb1);                                    \
        cp16(s0 + 3u * TILE_U16 * 2u, Bl + gb0);                                    \
        cp16(s1 + 3u * TILE_U16 * 2u, Bl + gb1);                                    \
    }

    LOAD_STAGE(0, 0u);
    CP_COMMIT();

    for (int ck = 0; ck < NCK; ck++) {
        if (ck + 1 < NCK) {
            LOAD_STAGE(ck + 1, (unsigned)(((ck + 1) & 1) * STAGE_U16 * 2));
            CP_COMMIT();
            CP_WAIT1();
        } else {
            CP_WAIT0();
        }
        __syncthreads();

        unsigned stage = sbase + (unsigned)((ck & 1) * STAGE_U16 * 2);
        unsigned aH = stage + aoffb;
        unsigned bH = stage + 2u * TILE_U16 * 2u + boffb;

#pragma unroll
        for (int ks = 0; ks < BK; ks += 16) {
            unsigned ksb = (unsigned)(ks * 2);
            unsigned ah[4][4], al[4][4], bh[4][2], bl[4][2];
#pragma unroll
            for (int mf = 0; mf < 4; mf++) {
                unsigned ra = aH + (unsigned)(mf * 16 * ASTR * 2) + ksb;
                ldsm_x4(ah[mf][0], ah[mf][1], ah[mf][2], ah[mf][3], ra);
                ldsm_x4(al[mf][0], al[mf][1], al[mf][2], al[mf][3], ra + TILE_U16 * 2u);
            }
#pragma unroll
            for (int np = 0; np < 2; np++) {
                unsigned rb = bH + (unsigned)(np * 16 * ASTR * 2) + ksb;
                ldsm_x4(bh[2 * np][0], bh[2 * np][1], bh[2 * np + 1][0], bh[2 * np + 1][1], rb);
                ldsm_x4(bl[2 * np][0], bl[2 * np][1], bl[2 * np + 1][0], bl[2 * np + 1][1],
                        rb + TILE_U16 * 2u);
            }
#pragma unroll
            for (int mf = 0; mf < 4; mf++)
#pragma unroll
                for (int nf = 0; nf < 4; nf++)
                    mma_bf16(acc[mf][nf], ah[mf], bh[nf]);
#pragma unroll
            for (int mf = 0; mf < 4; mf++)
#pragma unroll
                for (int nf = 0; nf < 4; nf++)
                    mma_bf16(acc[mf][nf], ah[mf], bl[nf]);
#pragma unroll
            for (int mf = 0; mf < 4; mf++)
#pragma unroll
                for (int nf = 0; nf < 4; nf++)
                    mma_bf16(acc[mf][nf], al[mf], bh[nf]);
        }
        __syncthreads();
    }

#pragma unroll
    for (int mf = 0; mf < 4; mf++) {
        int r0 = m0 + wm + mf * 16 + g;
#pragma unroll
        for (int nf = 0; nf < 4; nf++) {
            int col = n0 + wn + nf * 8 + tc2;
            float bx = bias[col], by = bias[col + 1];
            float2 lo = make_float2(acc[mf][nf][0] + bx, acc[mf][nf][1] + by);
            float2 hi = make_float2(acc[mf][nf][2] + bx, acc[mf][nf][3] + by);
            *(float2*)(Co + (size_t)r0 * CCH + col) = lo;
            *(float2*)(Co + (size_t)(r0 + 8) * CCH + col) = hi;
        }
    }
}

// ================= fp16 single-pass GEMM (V, out) ================================
#define F1STAGE_U16 (2 * TILE_U16)
#define F1SMEM (2 * F1STAGE_U16 * 2)

__global__ __launch_bounds__(256, 2) void gemm_f1(
    const unsigned short* __restrict__ Ah, const unsigned short* __restrict__ Bh,
    const float* __restrict__ bias, float* __restrict__ Co,
    unsigned short* __restrict__ OH)
{
    extern __shared__ __align__(16) unsigned short smg[];
    unsigned sbase = smem_u32(smg);

    int tid = threadIdx.x, w = tid >> 5, lane = tid & 31;
    int g = lane >> 2, tc2 = (lane & 3) * 2;
    int m0 = blockIdx.y * BM, n0 = blockIdx.x * BN;
    int wm = (w >> 2) * 64, wn = (w & 3) * 32;

    float acc[4][4][4];
#pragma unroll
    for (int i = 0; i < 4; i++)
#pragma unroll
        for (int j = 0; j < 4; j++)
#pragma unroll
            for (int l = 0; l < 4; l++) acc[i][j][l] = 0.f;

    int r0l = tid >> 2, c0l = (tid & 3) * 8;
    int r1l = (tid + 256) >> 2, c1l = ((tid + 256) & 3) * 8;

    unsigned aoffb = (unsigned)(((wm + (lane & 15)) * ASTR + ((lane >> 1) & 8)) * 2);
    unsigned boffb = (unsigned)(((wn + (lane & 7) + ((lane >> 1) & 8)) * ASTR + (lane & 8)) * 2);

    const int NCK = CCH / BK;

#define F1_LOAD(CK, SOFF)                                                           \
    {                                                                               \
        int kb = (CK) * BK;                                                         \
        unsigned s0 = sbase + (SOFF) + (unsigned)(r0l * ASTR + c0l) * 2u;           \
        unsigned s1 = sbase + (SOFF) + (unsigned)(r1l * ASTR + c1l) * 2u;           \
        size_t ga0 = (size_t)(m0 + r0l) * CCH + kb + c0l;                           \
        size_t ga1 = (size_t)(m0 + r1l) * CCH + kb + c1l;                           \
        size_t gb0 = (size_t)(n0 + r0l) * CCH + kb + c0l;                           \
        size_t gb1 = (size_t)(n0 + r1l) * CCH + kb + c1l;                           \
        cp16(s0, Ah + ga0);                                                         \
        cp16(s1, Ah + ga1);                                                         \
        cp16(s0 + TILE_U16 * 2u, Bh + gb0);                                         \
        cp16(s1 + TILE_U16 * 2u, Bh + gb1);                                         \
    }

    F1_LOAD(0, 0u);
    CP_COMMIT();

    for (int ck = 0; ck < NCK; ck++) {
        if (ck + 1 < NCK) {
            F1_LOAD(ck + 1, (unsigned)(((ck + 1) & 1) * F1STAGE_U16 * 2));
            CP_COMMIT();
            CP_WAIT1();
        } else {
            CP_WAIT0();
        }
        __syncthreads();

        unsigned stage = sbase + (unsigned)((ck & 1) * F1STAGE_U16 * 2);
        unsigned aH = stage + aoffb;
        unsigned bH = stage + TILE_U16 * 2u + boffb;

#pragma unroll
        for (int ks = 0; ks < BK; ks += 16) {
            unsigned ksb = (unsigned)(ks * 2);
            unsigned ah[4][4], bh[4][2];
#pragma unroll
            for (int mf = 0; mf < 4; mf++) {
                unsigned ra = aH + (unsigned)(mf * 16 * ASTR * 2) + ksb;
                ldsm_x4(ah[mf][0], ah[mf][1], ah[mf][2], ah[mf][3], ra);
            }
#pragma unroll
            for (int np = 0; np < 2; np++) {
                unsigned rb = bH + (unsigned)(np * 16 * ASTR * 2) + ksb;
                ldsm_x4(bh[2 * np][0], bh[2 * np][1], bh[2 * np + 1][0], bh[2 * np + 1][1], rb);
            }
#pragma unroll
            for (int mf = 0; mf < 4; mf++)
#pragma unroll
                for (int nf = 0; nf < 4; nf++)
                    mma_f16(acc[mf][nf], ah[mf], bh[nf]);
        }
        __syncthreads();
    }

    if (OH == nullptr) {
#pragma unroll
        for (int mf = 0; mf < 4; mf++) {
            int r0 = m0 + wm + mf * 16 + g;
#pragma unroll
            for (int nf = 0; nf < 4; nf++) {
                int col = n0 + wn + nf * 8 + tc2;
                float bx = bias[col], by = bias[col + 1];
                float2 lo = make_float2(acc[mf][nf][0] + bx, acc[mf][nf][1] + by);
                float2 hi = make_float2(acc[mf][nf][2] + bx, acc[mf][nf][3] + by);
                *(float2*)(Co + (size_t)r0 * CCH + col) = lo;
                *(float2*)(Co + (size_t)(r0 + 8) * CCH + col) = hi;
            }
        }
    } else {
#pragma unroll
        for (int mf = 0; mf < 4; mf++) {
            int r0 = m0 + wm + mf * 16 + g;
#pragma unroll
            for (int nf = 0; nf < 4; nf++) {
                int col = n0 + wn + nf * 8 + tc2;
                float bx = bias[col], by = bias[col + 1];
                *(unsigned*)&OH[(size_t)r0 * CCH + col] =
                    pack_f16x2(acc[mf][nf][0] + bx, acc[mf][nf][1] + by);
                *(unsigned*)&OH[(size_t)(r0 + 8) * CCH + col] =
                    pack_f16x2(acc[mf][nf][2] + bx, acc[mf][nf][3] + by);
            }
        }
    }
}

// ---------------- fused RMSNorm + RoPE + fp16 store (q+k z-merged) --------------
struct RNPtrs {
    float* buf[2];
    const float* w[2];
    unsigned short* oh[2];
};

__global__ __launch_bounds__(256) void rmsnorm_rope_f16(
    RNPtrs P, const float* __restrict__ cs, const float* __restrict__ sn)
{
    int z = blockIdx.y;
    float* __restrict__ bufz = P.buf[z];
    const float* __restrict__ w = P.w[z];
    unsigned short* __restrict__ oh = P.oh[z];

    int warp = (blockIdx.x * blockDim.x + threadIdx.x) >> 5;
    int lane = threadIdx.x & 31;
    if (warp >= SQ * NH) return;
    int s = warp / NH, h = warp % NH;
    size_t base = (size_t)s * CCH + h * HD;
    float* row = bufz + base;

    float x0 = row[lane], x1 = row[lane + 32], x2 = row[lane + 64], x3 = row[lane + 96];
    float ss = x0 * x0 + x1 * x1 + x2 * x2 + x3 * x3;
#pragma unroll
    for (int o = 16; o; o >>= 1) ss += __shfl_xor_sync(0xffffffffu, ss, o);
    float r = rsqrtf(ss * (1.0f / HD) + EPSV);

    float y0 = x0 * r * w[lane];
    float y1 = x1 * r * w[lane + 32];
    float y2 = x2 * r * w[lane + 64];
    float y3 = x3 * r * w[lane + 96];

    const float* cr = cs + (size_t)s * HD;
    const float* sr = sn + (size_t)s * HD;
    float z0 = y0 * cr[lane]      - y2 * sr[lane];
    float z1 = y1 * cr[lane + 32] - y3 * sr[lane + 32];
    float z2 = y2 * cr[lane + 64] + y0 * sr[lane + 64];
    float z3 = y3 * cr[lane + 96] + y1 * sr[lane + 96];

    row[lane] = z0; row[lane + 32] = z1; row[lane + 64] = z2; row[lane + 96] = z3;

    oh[base + lane]      = __half_as_ushort(__float2half_rn(z0));
    oh[base + lane + 32] = __half_as_ushort(__float2half_rn(z1));
    oh[base + lane + 64] = __half_as_ushort(__float2half_rn(z2));
    oh[base + lane + 96] = __half_as_ushort(__float2half_rn(z3));
}

// ---------------- block pooling (q+k z-merged) -----------------------------------
struct PoolPtrs {
    const float* in[2];
    float* out[2];
};

__global__ void pool_blocks(PoolPtrs P)
{
    int z = blockIdx.z;
    const float* buf = P.in[z];
    float* out = P.out[z];
    int h = blockIdx.x, b = blockIdx.y, d = threadIdx.x;
    float sum = 0.f;
#pragma unroll 8
    for (int i = 0; i < BLKS; i++)
        sum += buf[(size_t)(b * BLKS + i) * CCH + h * HD + d];
    out[((h * NB) + b) * HD + d] = sum * (1.0f / BLKS);
}

// ---------------- NABLA block mask ----------------------------------------------
__device__ __forceinline__ int sniff_sta_dtype(const unsigned int* w)
{
    bool all01 = true, allf = true;
    for (int i = 0; i < 256; i++) {
        unsigned int v = w[i];
        if (v > 1u) all01 = false;
        if (v != 0u && v != 0x3F800000u) allf = false;
    }
    if (all01) return 0;
    if (allf) return 1;
    return 2;
}

__global__ void nabla_mask(const float* __restrict__ qb, const float* __restrict__ kb,
                           const void* __restrict__ sta, unsigned char* __restrict__ mask)
{
    int h = blockIdx.x, q = blockIdx.y, k = threadIdx.x;
    __shared__ float p[NB];
    __shared__ float cutoff;
    __shared__ int sdt;
    if (k == 0) sdt = sniff_sta_dtype((const unsigned int*)sta);

    const float* qr = qb + (h * NB + q) * HD;
    const float* kr = kb + (h * NB + k) * HD;
    float dot = 0.f;
#pragma unroll 16
    for (int d = 0; d < HD; d++) dot += qr[d] * kr[d];
    p[k] = dot * 0.08838834764831845f;
    __syncthreads();
    if (k == 0) {
        float mx = -1e30f;
        for (int i = 0; i < NB; i++) mx = fmaxf(mx, p[i]);
        float sum = 0.f;
        for (int i = 0; i < NB; i++) { p[i] = expf(p[i] - mx); sum += p[i]; }
        float inv = 1.0f / sum;
        float srt[NB];
        for (int i = 0; i < NB; i++) { p[i] *= inv; srt[i] = p[i]; }
        for (int i = 1; i < NB; i++) {
            float v = srt[i];
            int j = i - 1;
            while (j >= 0 && srt[j] < v) { srt[j + 1] = srt[j]; j--; }
            srt[j + 1] = v;
        }
        float run = 0.f, co = 1e30f;
        for (int i = 0; i < NB; i++) {
            if (run < THRP) { co = srt[i]; run += srt[i]; }
        }
        cutoff = co;
    }
    __syncthreads();

    bool sta_on;
    int sidx = q * NB + k;
    if (sdt == 0)      sta_on = ((const int*)sta)[sidx] != 0;
    else if (sdt == 1) sta_on = ((const float*)sta)[sidx] != 0.0f;
    else               sta_on = ((const unsigned char*)sta)[sidx] != 0;

    unsigned char keep = (p[k] >= cutoff) || sta_on;
    mask[(h * NB + q) * NB + k] = keep;
}

// ---------------- fp16 single-pass flash attention (double-buffered K+V) --------
#define KSTR 136
#define BUF_U16 (64 * KSTR)
#define FF_SMEM (4 * BUF_U16 * 2)   // K0,V0,K1,V1

__global__ __launch_bounds__(128) void flash_f16(
    const unsigned short* __restrict__ qf, const unsigned short* __restrict__ kf,
    const unsigned short* __restrict__ vf, const unsigned char* __restrict__ mask,
    unsigned short* __restrict__ oh)
{
    extern __shared__ __align__(16) unsigned short smu[];

    int qi = blockIdx.x, h = blockIdx.y;
    int tid = threadIdx.x, w = tid >> 5, lane = tid & 31;
    int g = lane >> 2, tc2 = (lane & 3) * 2;
    int wr = w * 16;

    for (int idx = tid; idx < 64 * 16; idx += 128) {
        int r = idx >> 4, c = (idx & 15) * 8;
        size_t off = (size_t)(qi * 64 + r) * CCH + h * HD + c;
        *(uint4*)&smu[r * KSTR + c] = *(const uint4*)(qf + off);
    }
    __syncthreads();

    unsigned qfr[8][4];
#pragma unroll
    for (int t = 0; t < 8; t++) {
        int r0 = (wr + g) * KSTR + 16 * t + tc2;
        int r8 = (wr + 8 + g) * KSTR + 16 * t + tc2;
        qfr[t][0] = *(const unsigned*)&smu[r0];
        qfr[t][1] = *(const unsigned*)&smu[r8];
        qfr[t][2] = *(const unsigned*)&smu[r0 + 8];
        qfr[t][3] = *(const unsigned*)&smu[r8 + 8];
    }
    __syncthreads();

    float acc[16][4];
#pragma unroll
    for (int nf = 0; nf < 16; nf++)
#pragma unroll
        for (int i = 0; i < 4; i++) acc[nf][i] = 0.f;
    float m0 = -1e30f, m1 = -1e30f, l0 = 0.f, l1 = 0.f;

    const unsigned char* mrowp = mask + (h * NB + qi) * NB;
    const float scl = 0.08838834764831845f;
    unsigned base_s = smem_u32(smu);
    int lj = lane >> 3, li = lane & 7;
    unsigned ldsm_off = (unsigned)(((lj & 1) * 8 + li) * KSTR + (lj >> 1) * 8) * 2u;

#define FF_LOAD(B, BUF)                                                              \
    {                                                                                \
        unsigned kb_s = base_s + (unsigned)((BUF) * 2 * BUF_U16) * 2u;               \
        unsigned vb_s = kb_s + (unsigned)BUF_U16 * 2u;                               \
        _Pragma("unroll")                                                            \
        for (int it = 0; it < 8; it++) {                                             \
            int idx = tid + it * 128;                                                \
            int r = idx >> 4, c = (idx & 15) * 8;                                    \
            size_t off = (size_t)((B) * 64 + r) * CCH + h * HD + c;                  \
            unsigned so = (unsigned)((r * KSTR + c) * 2);                            \
            cp16(kb_s + so, kf + off);                                               \
            cp16(vb_s + so, vf + off);                                               \
        }                                                                            \
        CP_COMMIT();                                                                 \
    }

    int cur = 0;
    while (cur < NB && !mrowp[cur]) cur++;
    int p = 0;
    if (cur < NB) {
        FF_LOAD(cur, 0);
        CP_WAIT0();
        __syncthreads();
    }

    while (cur < NB) {
        int nxt = cur + 1;
        while (nxt < NB && !mrowp[nxt]) nxt++;
        if (nxt < NB) FF_LOAD(nxt, p ^ 1);

        const unsigned short* Kc = smu + p * 2 * BUF_U16;
        unsigned v_s = base_s + (unsigned)(p * 2 * BUF_U16 + BUF_U16) * 2u;

        float sc[8][4];
#pragma unroll
        for (int j = 0; j < 8; j++)
#pragma unroll
            for (int i = 0; i < 4; i++) sc[j][i] = 0.f;

#pragma unroll
        for (int t = 0; t < 8; t++) {
#pragma unroll
            for (int j = 0; j < 8; j++) {
                int rbase = (8 * j + g) * KSTR + 16 * t;
                unsigned bh[2];
                bh[0] = *(const unsigned*)&Kc[rbase + tc2];
                bh[1] = *(const unsigned*)&Kc[rbase + 8 + tc2];
                mma_f16(sc[j], qfr[t], bh);
            }
        }

        float rm0 = -1e30f, rm1 = -1e30f;
#pragma unroll
        for (int j = 0; j < 8; j++) {
#pragma unroll
            for (int i = 0; i < 4; i++) sc[j][i] *= scl;
            rm0 = fmaxf(rm0, fmaxf(sc[j][0], sc[j][1]));
            rm1 = fmaxf(rm1, fmaxf(sc[j][2], sc[j][3]));
        }
        rm0 = fmaxf(rm0, __shfl_xor_sync(0xffffffffu, rm0, 1));
        rm0 = fmaxf(rm0, __shfl_xor_sync(0xffffffffu, rm0, 2));
        rm1 = fmaxf(rm1, __shfl_xor_sync(0xffffffffu, rm1, 1));
        rm1 = fmaxf(rm1, __shfl_xor_sync(0xffffffffu, rm1, 2));
        float mn0 = fmaxf(m0, rm0), mn1 = fmaxf(m1, rm1);
        float es0 = __expf(m0 - mn0), es1 = __expf(m1 - mn1);

        float rs0 = 0.f, rs1 = 0.f;
#pragma unroll
        for (int j = 0; j < 8; j++) {
            sc[j][0] = __expf(sc[j][0] - mn0);
            sc[j][1] = __expf(sc[j][1] - mn0);
            sc[j][2] = __expf(sc[j][2] - mn1);
            sc[j][3] = __expf(sc[j][3] - mn1);
            rs0 += sc[j][0] + sc[j][1];
            rs1 += sc[j][2] + sc[j][3];
        }
        rs0 += __shfl_xor_sync(0xffffffffu, rs0, 1);
        rs0 += __shfl_xor_sync(0xffffffffu, rs0, 2);
        rs1 += __shfl_xor_sync(0xffffffffu, rs1, 1);
        rs1 += __shfl_xor_sync(0xffffffffu, rs1, 2);
        l0 = l0 * es0 + rs0;
        l1 = l1 * es1 + rs1;
        m0 = mn0; m1 = mn1;
#pragma unroll
        for (int nf = 0; nf < 16; nf++) {
            acc[nf][0] *= es0; acc[nf][1] *= es0;
            acc[nf][2] *= es1; acc[nf][3] *= es1;
        }

#pragma unroll
        for (int t = 0; t < 4; t++) {
            unsigned ph[4];
            ph[0] = pack_f16x2(sc[2 * t][0], sc[2 * t][1]);
            ph[1] = pack_f16x2(sc[2 * t][2], sc[2 * t][3]);
            ph[2] = pack_f16x2(sc[2 * t + 1][0], sc[2 * t + 1][1]);
            ph[3] = pack_f16x2(sc[2 * t + 1][2], sc[2 * t + 1][3]);
            unsigned trow = (unsigned)(16 * t * KSTR) * 2u + ldsm_off;
#pragma unroll
            for (int nfp = 0; nfp < 8; nfp++) {
                unsigned v0r, v1r, v2r, v3r;
                ldsm_x4_t(v0r, v1r, v2r, v3r, v_s + trow + (unsigned)(16 * nfp) * 2u);
                unsigned bh0[2] = {v0r, v1r}, bh1[2] = {v2r, v3r};
                mma_f16(acc[2 * nfp], ph, bh0);
                mma_f16(acc[2 * nfp + 1], ph, bh1);
            }
        }

        if (nxt < NB) CP_WAIT0();
        __syncthreads();
        p ^= 1;
        cur = nxt;
    }

    // epilogue: normalize + fp16 store for out-proj
    float inv0 = 1.0f / l0, inv1 = 1.0f / l1;
    int r0 = qi * 64 + wr + g;
    size_t ob = (size_t)r0 * CCH + h * HD;
#pragma unroll
    for (int nf = 0; nf < 16; nf++) {
        int col = 8 * nf + tc2;
        *(unsigned*)&oh[ob + col] =
            pack_f16x2(acc[nf][0] * inv0, acc[nf][1] * inv0);
        *(unsigned*)&oh[ob + 8 * CCH + col] =
            pack_f16x2(acc[nf][2] * inv1, acc[nf][3] * inv1);
    }
}

// ---------------- launch ----------------------------------------------------------
extern "C" void kernel_launch(void* const* d_in, const int* in_sizes, int n_in,
                              void* d_out, int out_size)
{
    const float* x        = (const float*)d_in[0];
    const float* rope_cos = (const float*)d_in[1];
    const float* rope_sin = (const float*)d_in[2];
    const void*  sta      = (const void*)d_in[3];
    const float* Wq = (const float*)d_in[4];
    const float* bq = (const float*)d_in[5];
    const float* Wk = (const float*)d_in[6];
    const float* bk = (const float*)d_in[7];
    const float* Wv = (const float*)d_in[8];
    const float* bv = (const float*)d_in[9];
    const float* Wo = (const float*)d_in[10];
    const float* bo = (const float*)d_in[11];
    const float* qn_w = (const float*)d_in[12];
    const float* kn_w = (const float*)d_in[13];
    float* out = (float*)d_out;

    float *qp, *kp, *qbp, *kbp;
    unsigned char* mp;
    unsigned short *xh, *xl, *xf, *af, *qfp, *kfp, *vfp;
    unsigned short *wqh, *wql, *wkh, *wkl, *wvh, *woh;
    cudaGetSymbolAddress((void**)&qp, g_q);
    cudaGetSymbolAddress((void**)&kp, g_k);
    cudaGetSymbolAddress((void**)&qbp, g_qb);
    cudaGetSymbolAddress((void**)&kbp, g_kb);
    cudaGetSymbolAddress((void**)&mp, g_mask);
    cudaGetSymbolAddress((void**)&xh, g_xh);
    cudaGetSymbolAddress((void**)&xl, g_xl);
    cudaGetSymbolAddress((void**)&xf, g_xf);
    cudaGetSymbolAddress((void**)&af, g_af);
    cudaGetSymbolAddress((void**)&qfp, g_qf);
    cudaGetSymbolAddress((void**)&kfp, g_kf);
    cudaGetSymbolAddress((void**)&vfp, g_vf);
    cudaGetSymbolAddress((void**)&wqh, g_wqh);
    cudaGetSymbolAddress((void**)&wql, g_wql);
    cudaGetSymbolAddress((void**)&wkh, g_wkh);
    cudaGetSymbolAddress((void**)&wkl, g_wkl);
    cudaGetSymbolAddress((void**)&wvh, g_wvh);
    cudaGetSymbolAddress((void**)&woh, g_woh);

    const int NEL = SQ * CCH;

    split_x<<<(NEL + 255) / 256, 256>>>(x, xh, xl, xf, NEL);

    TransPtrs tp;
    tp.w[0] = Wq; tp.w[1] = Wk; tp.w[2] = Wv; tp.w[3] = Wo;
    tp.th[0] = wqh; tp.th[1] = wkh; tp.th[2] = wvh; tp.th[3] = woh;
    tp.tl[0] = wql; tp.tl[1] = wkl; tp.tl[2] = nullptr; tp.tl[3] = nullptr;
    transpose_split4<<<dim3(CCH / 32, CCH / 32, 4), dim3(32, 32)>>>(tp);

    cudaFuncSetAttribute(gemm_bf3, cudaFuncAttributeMaxDynamicSharedMemorySize, G2SMEM);
    cudaFuncSetAttribute(gemm_f1, cudaFuncAttributeMaxDynamicSharedMemorySize, F1SMEM);
    dim3 ggrid(CCH / BN, SQ / BM);

    Gemm2 gqk;
    gqk.bh[0] = wqh; gqk.bh[1] = wkh;
    gqk.bl[0] = wql; gqk.bl[1] = wkl;
    gqk.bias[0] = bq; gqk.bias[1] = bk;
    gqk.out[0] = qp; gqk.out[1] = kp;
    gemm_bf3<<<dim3(CCH / BN, SQ / BM, 2), 256, G2SMEM>>>(xh, xl, gqk);

    gemm_f1<<<ggrid, 256, F1SMEM>>>(xf, wvh, bv, nullptr, vfp);

    RNPtrs rn;
    rn.buf[0] = qp; rn.buf[1] = kp;
    rn.w[0] = qn_w; rn.w[1] = kn_w;
    rn.oh[0] = qfp; rn.oh[1] = kfp;
    int nwarp_blocks = (SQ * NH) / 8;
    rmsnorm_rope_f16<<<dim3(nwarp_blocks, 2), 256>>>(rn, rope_cos, rope_sin);

    PoolPtrs pp;
    pp.in[0] = qp; pp.in[1] = kp;
    pp.out[0] = qbp; pp.out[1] = kbp;
    pool_blocks<<<dim3(NH, NB, 2), 128>>>(pp);

    nabla_mask<<<dim3(NH, NB), 32>>>(qbp, kbp, sta, mp);

    cudaFuncSetAttribute(flash_f16, cudaFuncAttributeMaxDynamicSharedMemorySize, FF_SMEM);
    flash_f16<<<dim3(NB, NH), 128, FF_SMEM>>>(qfp, kfp, vfp, mp, af);

    gemm_f1<<<ggrid, 256, F1SMEM>>>(af, woh, bo, out, nullptr);
}

// round 16
// speedup vs baseline: 1.5231x; 1.0554x over previous
#include <cuda_runtime.h>
#include <cuda_bf16.h>
#include <cuda_fp16.h>
#include <math.h>

#define SQ   2048
#define CCH  2048
#define NH   16
#define HD   128
#define BLKS 64
#define NB   32
#define THRP 0.8f
#define EPSV 1e-6f

// ---------------- scratch (device globals; no allocation allowed) -------------
__device__ float g_q[SQ * CCH];
__device__ float g_k[SQ * CCH];
__device__ float g_qb[NH * NB * HD];
__device__ float g_kb[NH * NB * HD];
__device__ unsigned char g_mask[NH * NB * NB];

__device__ unsigned short g_xh[SQ * CCH];
__device__ unsigned short g_xl[SQ * CCH];
__device__ unsigned short g_xf[SQ * CCH];
__device__ unsigned short g_af[SQ * CCH];
__device__ unsigned short g_qf[SQ * CCH];
__device__ unsigned short g_kf[SQ * CCH];
__device__ unsigned short g_vf[SQ * CCH];
__device__ unsigned short g_wqh[CCH * CCH];
__device__ unsigned short g_wql[CCH * CCH];
__device__ unsigned short g_wkh[CCH * CCH];
__device__ unsigned short g_wkl[CCH * CCH];
__device__ unsigned short g_wvh[CCH * CCH];
__device__ unsigned short g_woh[CCH * CCH];

// ================= helpers ======================================================
__device__ __forceinline__ unsigned pack_f16x2(float lo, float hi) {
    unsigned r;
    asm("cvt.rn.f16x2.f32 %0, %1, %2;" : "=r"(r) : "f"(hi), "f"(lo));
    return r;
}
__device__ __forceinline__ unsigned smem_u32(const void* p) {
    unsigned a;
    asm("{ .reg .u64 t; cvta.to.shared.u64 t, %1; cvt.u32.u64 %0, t; }" : "=r"(a) : "l"(p));
    return a;
}
__device__ __forceinline__ void mma_bf16(float* c, const unsigned* a, const unsigned* b)
{
    asm volatile(
        "mma.sync.aligned.m16n8k16.row.col.f32.bf16.bf16.f32 "
        "{%0,%1,%2,%3}, {%4,%5,%6,%7}, {%8,%9}, {%0,%1,%2,%3};"
        : "+f"(c[0]), "+f"(c[1]), "+f"(c[2]), "+f"(c[3])
        : "r"(a[0]), "r"(a[1]), "r"(a[2]), "r"(a[3]), "r"(b[0]), "r"(b[1]));
}
__device__ __forceinline__ void mma_f16(float* c, const unsigned* a, const unsigned* b)
{
    asm volatile(
        "mma.sync.aligned.m16n8k16.row.col.f32.f16.f16.f32 "
        "{%0,%1,%2,%3}, {%4,%5,%6,%7}, {%8,%9}, {%0,%1,%2,%3};"
        : "+f"(c[0]), "+f"(c[1]), "+f"(c[2]), "+f"(c[3])
        : "r"(a[0]), "r"(a[1]), "r"(a[2]), "r"(a[3]), "r"(b[0]), "r"(b[1]));
}
__device__ __forceinline__ void ldsm_x4(unsigned& r0, unsigned& r1, unsigned& r2, unsigned& r3,
                                        unsigned addr)
{
    asm volatile("ldmatrix.sync.aligned.m8n8.x4.shared.b16 {%0,%1,%2,%3}, [%4];"
                 : "=r"(r0), "=r"(r1), "=r"(r2), "=r"(r3) : "r"(addr));
}
__device__ __forceinline__ void ldsm_x4_t(unsigned& r0, unsigned& r1, unsigned& r2, unsigned& r3,
                                          unsigned addr)
{
    asm volatile("ldmatrix.sync.aligned.m8n8.x4.trans.shared.b16 {%0,%1,%2,%3}, [%4];"
                 : "=r"(r0), "=r"(r1), "=r"(r2), "=r"(r3) : "r"(addr));
}
__device__ __forceinline__ void cp16(unsigned sm, const void* g) {
    asm volatile("cp.async.cg.shared.global [%0], [%1], 16;" :: "r"(sm), "l"(g));
}
#define CP_COMMIT() asm volatile("cp.async.commit_group;" ::: "memory")
#define CP_WAIT0()  asm volatile("cp.async.wait_group 0;" ::: "memory")
#define CP_WAIT1()  asm volatile("cp.async.wait_group 1;" ::: "memory")

// ================= x split ======================================================
__global__ void split_x(const float* __restrict__ a,
                        unsigned short* __restrict__ bh, unsigned short* __restrict__ bl,
                        unsigned short* __restrict__ fh, int n)
{
    int i = blockIdx.x * 256 + threadIdx.x;
    if (i < n) {
        float v = a[i];
        __nv_bfloat16 hb = __float2bfloat16(v);
        bh[i] = __bfloat16_as_ushort(hb);
        bl[i] = __bfloat16_as_ushort(__float2bfloat16(v - __bfloat162float(hb)));
        fh[i] = __half_as_ushort(__float2half_rn(v));
    }
}

// ================= transpose + split ============================================
struct TransPtrs {
    const float* w[4];
    unsigned short* th[4];
    unsigned short* tl[4];
};

__global__ void transpose_split4(TransPtrs P)
{
    __shared__ float t[32][33];
    int z = blockIdx.z;
    const float* W = P.w[z];
    unsigned short* Th = P.th[z];
    unsigned short* Tl = P.tl[z];
    int bx = blockIdx.x * 32, by = blockIdx.y * 32;
    int tx = threadIdx.x, ty = threadIdx.y;
    t[ty][tx] = W[(size_t)(by + ty) * CCH + bx + tx];
    __syncthreads();
    float v = t[tx][ty];
    size_t o = (size_t)(bx + ty) * CCH + by + tx;
    if (Tl != nullptr) {
        __nv_bfloat16 hi = __float2bfloat16(v);
        Th[o] = __bfloat16_as_ushort(hi);
        Tl[o] = __bfloat16_as_ushort(__float2bfloat16(v - __bfloat162float(hi)));
    } else {
        Th[o] = __half_as_ushort(__float2half_rn(v));
    }
}

// ================= merged QKV GEMM ===============================================
// z=0,1: bf16x3 (Q,K) -> fp32 out.  z=2: fp16 single (V) -> fp16 out.
#define BM 128
#define BN 128
#define BK 32
#define ASTR 40
#define TILE_U16 (128 * ASTR)
#define STAGE_U16 (4 * TILE_U16)
#define G2SMEM (2 * STAGE_U16 * 2)

struct GemmQKV {
    const unsigned short* bh[3];
    const unsigned short* bl[2];
    const float* bias[3];
    float* outF[2];
    unsigned short* outV;
};

__global__ __launch_bounds__(256, 2) void gemm_qkv(
    const unsigned short* __restrict__ Abh, const unsigned short* __restrict__ Abl,
    const unsigned short* __restrict__ Af, GemmQKV P)
{
    extern __shared__ __align__(16) unsigned short smg[];
    unsigned sbase = smem_u32(smg);

    int z = blockIdx.z;
    int tid = threadIdx.x, w = tid >> 5, lane = tid & 31;
    int g = lane >> 2, tc2 = (lane & 3) * 2;
    int m0 = blockIdx.y * BM, n0 = blockIdx.x * BN;
    int wm = (w >> 2) * 64, wn = (w & 3) * 32;

    float acc[4][4][4];
#pragma unroll
    for (int i = 0; i < 4; i++)
#pragma unroll
        for (int j = 0; j < 4; j++)
#pragma unroll
            for (int l = 0; l < 4; l++) acc[i][j][l] = 0.f;

    int r0l = tid >> 2, c0l = (tid & 3) * 8;
    int r1l = (tid + 256) >> 2, c1l = ((tid + 256) & 3) * 8;

    unsigned aoffb = (unsigned)(((wm + (lane & 15)) * ASTR + ((lane >> 1) & 8)) * 2);
    unsigned boffb = (unsigned)(((wn + (lane & 7) + ((lane >> 1) & 8)) * ASTR + (lane & 8)) * 2);

    const int NCK = CCH / BK;

    if (z < 2) {
        const unsigned short* __restrict__ Bh = P.bh[z];
        const unsigned short* __restrict__ Bl = P.bl[z];
        const float* __restrict__ bias = P.bias[z];
        float* __restrict__ Co = P.outF[z];

#define LOAD_STAGE(CK, SOFF)                                                        \
    {                                                                               \
        int kb = (CK) * BK;                                                         \
        unsigned s0 = sbase + (SOFF) + (unsigned)(r0l * ASTR + c0l) * 2u;           \
        unsigned s1 = sbase + (SOFF) + (unsigned)(r1l * ASTR + c1l) * 2u;           \
        size_t ga0 = (size_t)(m0 + r0l) * CCH + kb + c0l;                           \
        size_t ga1 = (size_t)(m0 + r1l) * CCH + kb + c1l;                           \
        size_t gb0 = (size_t)(n0 + r0l) * CCH + kb + c0l;                           \
        size_t gb1 = (size_t)(n0 + r1l) * CCH + kb + c1l;                           \
        cp16(s0, Abh + ga0);                                                        \
        cp16(s1, Abh + ga1);                                                        \
        cp16(s0 + TILE_U16 * 2u, Abl + ga0);                                        \
        cp16(s1 + TILE_U16 * 2u, Abl + ga1);                                        \
        cp16(s0 + 2u * TILE_U16 * 2u, Bh + gb0);                                    \
        cp16(s1 + 2u * TILE_U16 * 2u, Bh + gb1);                                    \
        cp16(s0 + 3u * TILE_U16 * 2u, Bl + gb0);                                    \
        cp16(s1 + 3u * TILE_U16 * 2u, Bl + gb1);                                    \
    }

        LOAD_STAGE(0, 0u);
        CP_COMMIT();

        for (int ck = 0; ck < NCK; ck++) {
            if (ck + 1 < NCK) {
                LOAD_STAGE(ck + 1, (unsigned)(((ck + 1) & 1) * STAGE_U16 * 2));
                CP_COMMIT();
                CP_WAIT1();
            } else {
                CP_WAIT0();
            }
            __syncthreads();

            unsigned stage = sbase + (unsigned)((ck & 1) * STAGE_U16 * 2);
            unsigned aH = stage + aoffb;
            unsigned bH = stage + 2u * TILE_U16 * 2u + boffb;

#pragma unroll
            for (int ks = 0; ks < BK; ks += 16) {
                unsigned ksb = (unsigned)(ks * 2);
                unsigned ah[4][4], al[4][4], bh[4][2], bl[4][2];
#pragma unroll
                for (int mf = 0; mf < 4; mf++) {
                    unsigned ra = aH + (unsigned)(mf * 16 * ASTR * 2) + ksb;
                    ldsm_x4(ah[mf][0], ah[mf][1], ah[mf][2], ah[mf][3], ra);
                    ldsm_x4(al[mf][0], al[mf][1], al[mf][2], al[mf][3], ra + TILE_U16 * 2u);
                }
#pragma unroll
                for (int np = 0; np < 2; np++) {
                    unsigned rb = bH + (unsigned)(np * 16 * ASTR * 2) + ksb;
                    ldsm_x4(bh[2 * np][0], bh[2 * np][1], bh[2 * np + 1][0], bh[2 * np + 1][1], rb);
                    ldsm_x4(bl[2 * np][0], bl[2 * np][1], bl[2 * np + 1][0], bl[2 * np + 1][1],
                            rb + TILE_U16 * 2u);
                }
#pragma unroll
                for (int mf = 0; mf < 4; mf++)
#pragma unroll
                    for (int nf = 0; nf < 4; nf++)
                        mma_bf16(acc[mf][nf], ah[mf], bh[nf]);
#pragma unroll
                for (int mf = 0; mf < 4; mf++)
#pragma unroll
                    for (int nf = 0; nf < 4; nf++)
                        mma_bf16(acc[mf][nf], ah[mf], bl[nf]);
#pragma unroll
                for (int mf = 0; mf < 4; mf++)
#pragma unroll
                    for (int nf = 0; nf < 4; nf++)
                        mma_bf16(acc[mf][nf], al[mf], bh[nf]);
            }
            __syncthreads();
        }

#pragma unroll
        for (int mf = 0; mf < 4; mf++) {
            int r0 = m0 + wm + mf * 16 + g;
#pragma unroll
            for (int nf = 0; nf < 4; nf++) {
                int col = n0 + wn + nf * 8 + tc2;
                float bx = bias[col], by = bias[col + 1];
                float2 lo = make_float2(acc[mf][nf][0] + bx, acc[mf][nf][1] + by);
                float2 hi = make_float2(acc[mf][nf][2] + bx, acc[mf][nf][3] + by);
                *(float2*)(Co + (size_t)r0 * CCH + col) = lo;
                *(float2*)(Co + (size_t)(r0 + 8) * CCH + col) = hi;
            }
        }
    } else {
        // fp16 single-pass V path
        const unsigned short* __restrict__ Bh = P.bh[2];
        const float* __restrict__ bias = P.bias[2];
        unsigned short* __restrict__ OH = P.outV;

#define F1_LOAD(CK, SOFF)                                                           \
    {                                                                               \
        int kb = (CK) * BK;                                                         \
        unsigned s0 = sbase + (SOFF) + (unsigned)(r0l * ASTR + c0l) * 2u;           \
        unsigned s1 = sbase + (SOFF) + (unsigned)(r1l * ASTR + c1l) * 2u;           \
        size_t ga0 = (size_t)(m0 + r0l) * CCH + kb + c0l;                           \
        size_t ga1 = (size_t)(m0 + r1l) * CCH + kb + c1l;                           \
        size_t gb0 = (size_t)(n0 + r0l) * CCH + kb + c0l;                           \
        size_t gb1 = (size_t)(n0 + r1l) * CCH + kb + c1l;                           \
        cp16(s0, Af + ga0);                                                         \
        cp16(s1, Af + ga1);                                                         \
        cp16(s0 + TILE_U16 * 2u, Bh + gb0);                                         \
        cp16(s1 + TILE_U16 * 2u, Bh + gb1);                                         \
    }

        F1_LOAD(0, 0u);
        CP_COMMIT();

        for (int ck = 0; ck < NCK; ck++) {
            if (ck + 1 < NCK) {
                F1_LOAD(ck + 1, (unsigned)(((ck + 1) & 1) * 2 * TILE_U16 * 2));
                CP_COMMIT();
                CP_WAIT1();
            } else {
                CP_WAIT0();
            }
            __syncthreads();

            unsigned stage = sbase + (unsigned)((ck & 1) * 2 * TILE_U16 * 2);
            unsigned aH = stage + aoffb;
            unsigned bH = stage + TILE_U16 * 2u + boffb;

#pragma unroll
            for (int ks = 0; ks < BK; ks += 16) {
                unsigned ksb = (unsigned)(ks * 2);
                unsigned ah[4][4], bh[4][2];
#pragma unroll
                for (int mf = 0; mf < 4; mf++) {
                    unsigned ra = aH + (unsigned)(mf * 16 * ASTR * 2) + ksb;
                    ldsm_x4(ah[mf][0], ah[mf][1], ah[mf][2], ah[mf][3], ra);
                }
#pragma unroll
                for (int np = 0; np < 2; np++) {
                    unsigned rb = bH + (unsigned)(np * 16 * ASTR * 2) + ksb;
                    ldsm_x4(bh[2 * np][0], bh[2 * np][1], bh[2 * np + 1][0], bh[2 * np + 1][1], rb);
                }
#pragma unroll
                for (int mf = 0; mf < 4; mf++)
#pragma unroll
                    for (int nf = 0; nf < 4; nf++)
                        mma_f16(acc[mf][nf], ah[mf], bh[nf]);
            }
            __syncthreads();
        }

#pragma unroll
        for (int mf = 0; mf < 4; mf++) {
            int r0 = m0 + wm + mf * 16 + g;
#pragma unroll
            for (int nf = 0; nf < 4; nf++) {
                int col = n0 + wn + nf * 8 + tc2;
                float bx = bias[col], by = bias[col + 1];
                *(unsigned*)&OH[(size_t)r0 * CCH + col] =
                    pack_f16x2(acc[mf][nf][0] + bx, acc[mf][nf][1] + by);
                *(unsigned*)&OH[(size_t)(r0 + 8) * CCH + col] =
                    pack_f16x2(acc[mf][nf][2] + bx, acc[mf][nf][3] + by);
            }
        }
    }
}

// ================= fp16 single-pass GEMM (out-proj) ==============================
#define F1STAGE_U16 (2 * TILE_U16)
#define F1SMEM (2 * F1STAGE_U16 * 2)

__global__ __launch_bounds__(256, 2) void gemm_f1(
    const unsigned short* __restrict__ Ah, const unsigned short* __restrict__ Bh,
    const float* __restrict__ bias, float* __restrict__ Co)
{
    extern __shared__ __align__(16) unsigned short smg[];
    unsigned sbase = smem_u32(smg);

    int tid = threadIdx.x, w = tid >> 5, lane = tid & 31;
    int g = lane >> 2, tc2 = (lane & 3) * 2;
    int m0 = blockIdx.y * BM, n0 = blockIdx.x * BN;
    int wm = (w >> 2) * 64, wn = (w & 3) * 32;

    float acc[4][4][4];
#pragma unroll
    for (int i = 0; i < 4; i++)
#pragma unroll
        for (int j = 0; j < 4; j++)
#pragma unroll
            for (int l = 0; l < 4; l++) acc[i][j][l] = 0.f;

    int r0l = tid >> 2, c0l = (tid & 3) * 8;
    int r1l = (tid + 256) >> 2, c1l = ((tid + 256) & 3) * 8;

    unsigned aoffb = (unsigned)(((wm + (lane & 15)) * ASTR + ((lane >> 1) & 8)) * 2);
    unsigned boffb = (unsigned)(((wn + (lane & 7) + ((lane >> 1) & 8)) * ASTR + (lane & 8)) * 2);

    const int NCK = CCH / BK;

#define FO_LOAD(CK, SOFF)                                                           \
    {                                                                               \
        int kb = (CK) * BK;                                                         \
        unsigned s0 = sbase + (SOFF) + (unsigned)(r0l * ASTR + c0l) * 2u;           \
        unsigned s1 = sbase + (SOFF) + (unsigned)(r1l * ASTR + c1l) * 2u;           \
        size_t ga0 = (size_t)(m0 + r0l) * CCH + kb + c0l;                           \
        size_t ga1 = (size_t)(m0 + r1l) * CCH + kb + c1l;                           \
        size_t gb0 = (size_t)(n0 + r0l) * CCH + kb + c0l;                           \
        size_t gb1 = (size_t)(n0 + r1l) * CCH + kb + c1l;                           \
        cp16(s0, Ah + ga0);                                                         \
        cp16(s1, Ah + ga1);                                                         \
        cp16(s0 + TILE_U16 * 2u, Bh + gb0);                                         \
        cp16(s1 + TILE_U16 * 2u, Bh + gb1);                                         \
    }

    FO_LOAD(0, 0u);
    CP_COMMIT();

    for (int ck = 0; ck < NCK; ck++) {
        if (ck + 1 < NCK) {
            FO_LOAD(ck + 1, (unsigned)(((ck + 1) & 1) * F1STAGE_U16 * 2));
            CP_COMMIT();
            CP_WAIT1();
        } else {
            CP_WAIT0();
        }
        __syncthreads();

        unsigned stage = sbase + (unsigned)((ck & 1) * F1STAGE_U16 * 2);
        unsigned aH = stage + aoffb;
        unsigned bH = stage + TILE_U16 * 2u + boffb;

#pragma unroll
        for (int ks = 0; ks < BK; ks += 16) {
            unsigned ksb = (unsigned)(ks * 2);
            unsigned ah[4][4], bh[4][2];
#pragma unroll
            for (int mf = 0; mf < 4; mf++) {
                unsigned ra = aH + (unsigned)(mf * 16 * ASTR * 2) + ksb;
                ldsm_x4(ah[mf][0], ah[mf][1], ah[mf][2], ah[mf][3], ra);
            }
#pragma unroll
            for (int np = 0; np < 2; np++) {
                unsigned rb = bH + (unsigned)(np * 16 * ASTR * 2) + ksb;
                ldsm_x4(bh[2 * np][0], bh[2 * np][1], bh[2 * np + 1][0], bh[2 * np + 1][1], rb);
            }
#pragma unroll
            for (int mf = 0; mf < 4; mf++)
#pragma unroll
                for (int nf = 0; nf < 4; nf++)
                    mma_f16(acc[mf][nf], ah[mf], bh[nf]);
        }
        __syncthreads();
    }

#pragma unroll
    for (int mf = 0; mf < 4; mf++) {
        int r0 = m0 + wm + mf * 16 + g;
#pragma unroll
        for (int nf = 0; nf < 4; nf++) {
            int col = n0 + wn + nf * 8 + tc2;
            float bx = bias[col], by = bias[col + 1];
            float2 lo = make_float2(acc[mf][nf][0] + bx, acc[mf][nf][1] + by);
            float2 hi = make_float2(acc[mf][nf][2] + bx, acc[mf][nf][3] + by);
            *(float2*)(Co + (size_t)r0 * CCH + col) = lo;
            *(float2*)(Co + (size_t)(r0 + 8) * CCH + col) = hi;
        }
    }
}

// ---------------- fused RMSNorm + RoPE + fp16 store (q+k z-merged) --------------
struct RNPtrs {
    float* buf[2];
    const float* w[2];
    unsigned short* oh[2];
};

__global__ __launch_bounds__(256) void rmsnorm_rope_f16(
    RNPtrs P, const float* __restrict__ cs, const float* __restrict__ sn)
{
    int z = blockIdx.y;
    float* __restrict__ bufz = P.buf[z];
    const float* __restrict__ w = P.w[z];
    unsigned short* __restrict__ oh = P.oh[z];

    int warp = (blockIdx.x * blockDim.x + threadIdx.x) >> 5;
    int lane = threadIdx.x & 31;
    if (warp >= SQ * NH) return;
    int s = warp / NH, h = warp % NH;
    size_t base = (size_t)s * CCH + h * HD;
    float* row = bufz + base;

    float x0 = row[lane], x1 = row[lane + 32], x2 = row[lane + 64], x3 = row[lane + 96];
    float ss = x0 * x0 + x1 * x1 + x2 * x2 + x3 * x3;
#pragma unroll
    for (int o = 16; o; o >>= 1) ss += __shfl_xor_sync(0xffffffffu, ss, o);
    float r = rsqrtf(ss * (1.0f / HD) + EPSV);

    float y0 = x0 * r * w[lane];
    float y1 = x1 * r * w[lane + 32];
    float y2 = x2 * r * w[lane + 64];
    float y3 = x3 * r * w[lane + 96];

    const float* cr = cs + (size_t)s * HD;
    const float* sr = sn + (size_t)s * HD;
    float z0 = y0 * cr[lane]      - y2 * sr[lane];
    float z1 = y1 * cr[lane + 32] - y3 * sr[lane + 32];
    float z2 = y2 * cr[lane + 64] + y0 * sr[lane + 64];
    float z3 = y3 * cr[lane + 96] + y1 * sr[lane + 96];

    row[lane] = z0; row[lane + 32] = z1; row[lane + 64] = z2; row[lane + 96] = z3;

    oh[base + lane]      = __half_as_ushort(__float2half_rn(z0));
    oh[base + lane + 32] = __half_as_ushort(__float2half_rn(z1));
    oh[base + lane + 64] = __half_as_ushort(__float2half_rn(z2));
    oh[base + lane + 96] = __half_as_ushort(__float2half_rn(z3));
}

// ---------------- block pooling (q+k z-merged) -----------------------------------
struct PoolPtrs {
    const float* in[2];
    float* out[2];
};

__global__ void pool_blocks(PoolPtrs P)
{
    int z = blockIdx.z;
    const float* buf = P.in[z];
    float* out = P.out[z];
    int h = blockIdx.x, b = blockIdx.y, d = threadIdx.x;
    float sum = 0.f;
#pragma unroll 8
    for (int i = 0; i < BLKS; i++)
        sum += buf[(size_t)(b * BLKS + i) * CCH + h * HD + d];
    out[((h * NB) + b) * HD + d] = sum * (1.0f / BLKS);
}

// ---------------- NABLA block mask ----------------------------------------------
__device__ __forceinline__ int sniff_sta_dtype(const unsigned int* w)
{
    bool all01 = true, allf = true;
    for (int i = 0; i < 256; i++) {
        unsigned int v = w[i];
        if (v > 1u) all01 = false;
        if (v != 0u && v != 0x3F800000u) allf = false;
    }
    if (all01) return 0;
    if (allf) return 1;
    return 2;
}

__global__ void nabla_mask(const float* __restrict__ qb, const float* __restrict__ kb,
                           const void* __restrict__ sta, unsigned char* __restrict__ mask)
{
    int h = blockIdx.x, q = blockIdx.y, k = threadIdx.x;
    __shared__ float p[NB];
    __shared__ float cutoff;
    __shared__ int sdt;
    if (k == 0) sdt = sniff_sta_dtype((const unsigned int*)sta);

    const float* qr = qb + (h * NB + q) * HD;
    const float* kr = kb + (h * NB + k) * HD;
    float dot = 0.f;
#pragma unroll 16
    for (int d = 0; d < HD; d++) dot += qr[d] * kr[d];
    p[k] = dot * 0.08838834764831845f;
    __syncthreads();
    if (k == 0) {
        float mx = -1e30f;
        for (int i = 0; i < NB; i++) mx = fmaxf(mx, p[i]);
        float sum = 0.f;
        for (int i = 0; i < NB; i++) { p[i] = expf(p[i] - mx); sum += p[i]; }
        float inv = 1.0f / sum;
        float srt[NB];
        for (int i = 0; i < NB; i++) { p[i] *= inv; srt[i] = p[i]; }
        for (int i = 1; i < NB; i++) {
            float v = srt[i];
            int j = i - 1;
            while (j >= 0 && srt[j] < v) { srt[j + 1] = srt[j]; j--; }
            srt[j + 1] = v;
        }
        float run = 0.f, co = 1e30f;
        for (int i = 0; i < NB; i++) {
            if (run < THRP) { co = srt[i]; run += srt[i]; }
        }
        cutoff = co;
    }
    __syncthreads();

    bool sta_on;
    int sidx = q * NB + k;
    if (sdt == 0)      sta_on = ((const int*)sta)[sidx] != 0;
    else if (sdt == 1) sta_on = ((const float*)sta)[sidx] != 0.0f;
    else               sta_on = ((const unsigned char*)sta)[sidx] != 0;

    unsigned char keep = (p[k] >= cutoff) || sta_on;
    mask[(h * NB + q) * NB + k] = keep;
}

// ---------------- fp16 flash attention: 2 q-blocks/CTA, 8 warps ------------------
#define KSTR 136
#define BUF_U16 (64 * KSTR)
#define FF_SMEM (4 * BUF_U16 * 2)   // K0,V0,K1,V1 (Q staged over K0+V0)

__global__ __launch_bounds__(256, 1) void flash_f16(
    const unsigned short* __restrict__ qf, const unsigned short* __restrict__ kf,
    const unsigned short* __restrict__ vf, const unsigned char* __restrict__ mask,
    unsigned short* __restrict__ oh)
{
    extern __shared__ __align__(16) unsigned short smu[];

    int qt = blockIdx.x, h = blockIdx.y;
    int tid = threadIdx.x, w = tid >> 5, lane = tid & 31;
    int g = lane >> 2, tc2 = (lane & 3) * 2;
    int wr = w * 16;                      // 0..112 within 128-row q-tile
    const unsigned char* mA = mask + (h * NB + qt * 2) * NB;
    const unsigned char* mB = mA + NB;
    const unsigned char* mW = (w < 4) ? mA : mB;

    // stage Q tile (128 rows) into first two buffers, extract fragments
    for (int idx = tid; idx < 128 * 16; idx += 256) {
        int r = idx >> 4, c = (idx & 15) * 8;
        size_t off = (size_t)(qt * 128 + r) * CCH + h * HD + c;
        *(uint4*)&smu[r * KSTR + c] = *(const uint4*)(qf + off);
    }
    __syncthreads();

    unsigned qfr[8][4];
#pragma unroll
    for (int t = 0; t < 8; t++) {
        int r0 = (wr + g) * KSTR + 16 * t + tc2;
        int r8 = (wr + 8 + g) * KSTR + 16 * t + tc2;
        qfr[t][0] = *(const unsigned*)&smu[r0];
        qfr[t][1] = *(const unsigned*)&smu[r8];
        qfr[t][2] = *(const unsigned*)&smu[r0 + 8];
        qfr[t][3] = *(const unsigned*)&smu[r8 + 8];
    }
    __syncthreads();

    float acc[16][4];
#pragma unroll
    for (int nf = 0; nf < 16; nf++)
#pragma unroll
        for (int i = 0; i < 4; i++) acc[nf][i] = 0.f;
    float m0 = -1e30f, m1 = -1e30f, l0 = 0.f, l1 = 0.f;

    const float scl = 0.08838834764831845f;
    unsigned base_s = smem_u32(smu);
    int lj = lane >> 3, li = lane & 7;
    unsigned ldsm_off = (unsigned)(((lj & 1) * 8 + li) * KSTR + (lj >> 1) * 8) * 2u;

#define FF_LOAD(B, BUF)                                                              \
    {                                                                                \
        unsigned kb_s = base_s + (unsigned)((BUF) * 2 * BUF_U16) * 2u;               \
        unsigned vb_s = kb_s + (unsigned)BUF_U16 * 2u;                               \
        _Pragma("unroll")                                                            \
        for (int it = 0; it < 4; it++) {                                             \
            int idx = tid + it * 256;                                                \
            int r = idx >> 4, c = (idx & 15) * 8;                                    \
            size_t off = (size_t)((B) * 64 + r) * CCH + h * HD + c;                  \
            unsigned so = (unsigned)((r * KSTR + c) * 2);                            \
            cp16(kb_s + so, kf + off);                                               \
            cp16(vb_s + so, vf + off);                                               \
        }                                                                            \
        CP_COMMIT();                                                                 \
    }

    int cur = 0;
    while (cur < NB && !(mA[cur] | mB[cur])) cur++;
    int p = 0;
    if (cur < NB) {
        FF_LOAD(cur, 0);
        CP_WAIT0();
        __syncthreads();
    }

    while (cur < NB) {
        int nxt = cur + 1;
        while (nxt < NB && !(mA[nxt] | mB[nxt])) nxt++;
        if (nxt < NB) FF_LOAD(nxt, p ^ 1);

        bool act = mW[cur] != 0;
        const unsigned short* Kc = smu + p * 2 * BUF_U16;
        unsigned v_s = base_s + (unsigned)(p * 2 * BUF_U16 + BUF_U16) * 2u;

        if (act) {
            float sc[8][4];
#pragma unroll
            for (int j = 0; j < 8; j++)
#pragma unroll
                for (int i = 0; i < 4; i++) sc[j][i] = 0.f;

#pragma unroll
            for (int t = 0; t < 8; t++) {
#pragma unroll
                for (int j = 0; j < 8; j++) {
                    int rbase = (8 * j + g) * KSTR + 16 * t;
                    unsigned bh[2];
                    bh[0] = *(const unsigned*)&Kc[rbase + tc2];
                    bh[1] = *(const unsigned*)&Kc[rbase + 8 + tc2];
                    mma_f16(sc[j], qfr[t], bh);
                }
            }

            float rm0 = -1e30f, rm1 = -1e30f;
#pragma unroll
            for (int j = 0; j < 8; j++) {
#pragma unroll
                for (int i = 0; i < 4; i++) sc[j][i] *= scl;
                rm0 = fmaxf(rm0, fmaxf(sc[j][0], sc[j][1]));
                rm1 = fmaxf(rm1, fmaxf(sc[j][2], sc[j][3]));
            }
            rm0 = fmaxf(rm0, __shfl_xor_sync(0xffffffffu, rm0, 1));
            rm0 = fmaxf(rm0, __shfl_xor_sync(0xffffffffu, rm0, 2));
            rm1 = fmaxf(rm1, __shfl_xor_sync(0xffffffffu, rm1, 1));
            rm1 = fmaxf(rm1, __shfl_xor_sync(0xffffffffu, rm1, 2));
            float mn0 = fmaxf(m0, rm0), mn1 = fmaxf(m1, rm1);
            float es0 = __expf(m0 - mn0), es1 = __expf(m1 - mn1);

            float rs0 = 0.f, rs1 = 0.f;
#pragma unroll
            for (int j = 0; j < 8; j++) {
                sc[j][0] = __expf(sc[j][0] - mn0);
                sc[j][1] = __expf(sc[j][1] - mn0);
                sc[j][2] = __expf(sc[j][2] - mn1);
                sc[j][3] = __expf(sc[j][3] - mn1);
                rs0 += sc[j][0] + sc[j][1];
                rs1 += sc[j][2] + sc[j][3];
            }
            rs0 += __shfl_xor_sync(0xffffffffu, rs0, 1);
            rs0 += __shfl_xor_sync(0xffffffffu, rs0, 2);
            rs1 += __shfl_xor_sync(0xffffffffu, rs1, 1);
            rs1 += __shfl_xor_sync(0xffffffffu, rs1, 2);
            l0 = l0 * es0 + rs0;
            l1 = l1 * es1 + rs1;
            m0 = mn0; m1 = mn1;
#pragma unroll
            for (int nf = 0; nf < 16; nf++) {
                acc[nf][0] *= es0; acc[nf][1] *= es0;
                acc[nf][2] *= es1; acc[nf][3] *= es1;
            }

#pragma unroll
            for (int t = 0; t < 4; t++) {
                unsigned ph[4];
                ph[0] = pack_f16x2(sc[2 * t][0], sc[2 * t][1]);
                ph[1] = pack_f16x2(sc[2 * t][2], sc[2 * t][3]);
                ph[2] = pack_f16x2(sc[2 * t + 1][0], sc[2 * t + 1][1]);
                ph[3] = pack_f16x2(sc[2 * t + 1][2], sc[2 * t + 1][3]);
                unsigned trow = (unsigned)(16 * t * KSTR) * 2u + ldsm_off;
#pragma unroll
                for (int nfp = 0; nfp < 8; nfp++) {
                    unsigned v0r, v1r, v2r, v3r;
                    ldsm_x4_t(v0r, v1r, v2r, v3r, v_s + trow + (unsigned)(16 * nfp) * 2u);
                    unsigned bh0[2] = {v0r, v1r}, bh1[2] = {v2r, v3r};
                    mma_f16(acc[2 * nfp], ph, bh0);
                    mma_f16(acc[2 * nfp + 1], ph, bh1);
                }
            }
        }

        if (nxt < NB) CP_WAIT0();
        __syncthreads();
        p ^= 1;
        cur = nxt;
    }

    // epilogue: normalize + fp16 store
    float inv0 = 1.0f / l0, inv1 = 1.0f / l1;
    int r0 = qt * 128 + wr + g;
    size_t ob = (size_t)r0 * CCH + h * HD;
#pragma unroll
    for (int nf = 0; nf < 16; nf++) {
        int col = 8 * nf + tc2;
        *(unsigned*)&oh[ob + col] =
            pack_f16x2(acc[nf][0] * inv0, acc[nf][1] * inv0);
        *(unsigned*)&oh[ob + 8 * CCH + col] =
            pack_f16x2(acc[nf][2] * inv1, acc[nf][3] * inv1);
    }
}

// ---------------- launch ----------------------------------------------------------
extern "C" void kernel_launch(void* const* d_in, const int* in_sizes, int n_in,
                              void* d_out, int out_size)
{
    const float* x        = (const float*)d_in[0];
    const float* rope_cos = (const float*)d_in[1];
    const float* rope_sin = (const float*)d_in[2];
    const void*  sta      = (const void*)d_in[3];
    const float* Wq = (const float*)d_in[4];
    const float* bq = (const float*)d_in[5];
    const float* Wk = (const float*)d_in[6];
    const float* bk = (const float*)d_in[7];
    const float* Wv = (const float*)d_in[8];
    const float* bv = (const float*)d_in[9];
    const float* Wo = (const float*)d_in[10];
    const float* bo = (const float*)d_in[11];
    const float* qn_w = (const float*)d_in[12];
    const float* kn_w = (const float*)d_in[13];
    float* out = (float*)d_out;

    float *qp, *kp, *qbp, *kbp;
    unsigned char* mp;
    unsigned short *xh, *xl, *xf, *af, *qfp, *kfp, *vfp;
    unsigned short *wqh, *wql, *wkh, *wkl, *wvh, *woh;
    cudaGetSymbolAddress((void**)&qp, g_q);
    cudaGetSymbolAddress((void**)&kp, g_k);
    cudaGetSymbolAddress((void**)&qbp, g_qb);
    cudaGetSymbolAddress((void**)&kbp, g_kb);
    cudaGetSymbolAddress((void**)&mp, g_mask);
    cudaGetSymbolAddress((void**)&xh, g_xh);
    cudaGetSymbolAddress((void**)&xl, g_xl);
    cudaGetSymbolAddress((void**)&xf, g_xf);
    cudaGetSymbolAddress((void**)&af, g_af);
    cudaGetSymbolAddress((void**)&qfp, g_qf);
    cudaGetSymbolAddress((void**)&kfp, g_kf);
    cudaGetSymbolAddress((void**)&vfp, g_vf);
    cudaGetSymbolAddress((void**)&wqh, g_wqh);
    cudaGetSymbolAddress((void**)&wql, g_wql);
    cudaGetSymbolAddress((void**)&wkh, g_wkh);
    cudaGetSymbolAddress((void**)&wkl, g_wkl);
    cudaGetSymbolAddress((void**)&wvh, g_wvh);
    cudaGetSymbolAddress((void**)&woh, g_woh);

    const int NEL = SQ * CCH;

    split_x<<<(NEL + 255) / 256, 256>>>(x, xh, xl, xf, NEL);

    TransPtrs tp;
    tp.w[0] = Wq; tp.w[1] = Wk; tp.w[2] = Wv; tp.w[3] = Wo;
    tp.th[0] = wqh; tp.th[1] = wkh; tp.th[2] = wvh; tp.th[3] = woh;
    tp.tl[0] = wql; tp.tl[1] = wkl; tp.tl[2] = nullptr; tp.tl[3] = nullptr;
    transpose_split4<<<dim3(CCH / 32, CCH / 32, 4), dim3(32, 32)>>>(tp);

    cudaFuncSetAttribute(gemm_qkv, cudaFuncAttributeMaxDynamicSharedMemorySize, G2SMEM);
    cudaFuncSetAttribute(gemm_f1, cudaFuncAttributeMaxDynamicSharedMemorySize, F1SMEM);

    GemmQKV gp;
    gp.bh[0] = wqh; gp.bh[1] = wkh; gp.bh[2] = wvh;
    gp.bl[0] = wql; gp.bl[1] = wkl;
    gp.bias[0] = bq; gp.bias[1] = bk; gp.bias[2] = bv;
    gp.outF[0] = qp; gp.outF[1] = kp;
    gp.outV = vfp;
    gemm_qkv<<<dim3(CCH / BN, SQ / BM, 3), 256, G2SMEM>>>(xh, xl, xf, gp);

    RNPtrs rn;
    rn.buf[0] = qp; rn.buf[1] = kp;
    rn.w[0] = qn_w; rn.w[1] = kn_w;
    rn.oh[0] = qfp; rn.oh[1] = kfp;
    int nwarp_blocks = (SQ * NH) / 8;
    rmsnorm_rope_f16<<<dim3(nwarp_blocks, 2), 256>>>(rn, rope_cos, rope_sin);

    PoolPtrs pp;
    pp.in[0] = qp; pp.in[1] = kp;
    pp.out[0] = qbp; pp.out[1] = kbp;
    pool_blocks<<<dim3(NH, NB, 2), 128>>>(pp);

    nabla_mask<<<dim3(NH, NB), 32>>>(qbp, kbp, sta, mp);

    cudaFuncSetAttribute(flash_f16, cudaFuncAttributeMaxDynamicSharedMemorySize, FF_SMEM);
    flash_f16<<<dim3(NB / 2, NH), 256, FF_SMEM>>>(qfp, kfp, vfp, mp, af);

    gemm_f1<<<dim3(CCH / BN, SQ / BM), 256, F1SMEM>>>(af, woh, bo, out);
}